// round 7
// baseline (speedup 1.0000x reference)
#include <cuda_runtime.h>
#include <cstdint>
#include <cmath>

// ---------------------------------------------------------------------------
// Problem constants
// ---------------------------------------------------------------------------
#define BB 4
#define SS 1024
#define DD 2048
#define HH 16
#define HDIM 128
#define II 8192
#define MTOK (BB*SS)

// ---------------------------------------------------------------------------
// Scratch
// ---------------------------------------------------------------------------
__device__ __align__(256) float g_xln1 [MTOK*DD];
__device__ __align__(256) float g_q    [MTOK*DD];
__device__ __align__(256) float g_k    [MTOK*DD];
__device__ __align__(256) float g_v    [MTOK*DD];
__device__ __align__(256) float g_scores[(long)BB*HH*SS*SS];
__device__ __align__(256) float g_attn [MTOK*DD];
__device__ __align__(256) float g_hidden[MTOK*DD];
__device__ __align__(256) float g_yln2 [MTOK*DD];
__device__ __align__(256) float g_mid  [MTOK*II];
__device__ __align__(256) float g_wqkv[3*DD*DD];   // packed fragments, N=6144 (NB8=768)
__device__ __align__(256) float g_wo[DD*DD];       // packed, NB8=256
__device__ __align__(256) float g_w1[II*DD];       // packed, NB8=1024, K=2048
__device__ __align__(256) float g_w2[DD*II];       // packed, NB8=256,  K=8192

// ---------------------------------------------------------------------------
// Helpers
// ---------------------------------------------------------------------------
__device__ __forceinline__ float to_tf32(float x) {
    float r;
    asm("cvt.rna.tf32.f32 %0, %1;" : "=f"(r) : "f"(x));
    return r;
}
__device__ __forceinline__ void cpa16(void* sdst, const void* gsrc) {
    uint32_t s = (uint32_t)__cvta_generic_to_shared(sdst);
    asm volatile("cp.async.cg.shared.global [%0], [%1], 16;" :: "r"(s), "l"(gsrc));
}
__device__ __forceinline__ void cp_commit() { asm volatile("cp.async.commit_group;"); }
__device__ __forceinline__ void cp_wait2()  { asm volatile("cp.async.wait_group 2;"); }
__device__ __forceinline__ void cp_wait3()  { asm volatile("cp.async.wait_group 3;"); }

__device__ __forceinline__ void mma_tf32(float c[4], const float a[4], const float b[2]) {
    const uint32_t* A = reinterpret_cast<const uint32_t*>(a);
    const uint32_t* Bp = reinterpret_cast<const uint32_t*>(b);
    asm volatile(
        "mma.sync.aligned.m16n8k8.row.col.f32.tf32.tf32.f32 "
        "{%0,%1,%2,%3}, {%4,%5,%6,%7}, {%8,%9}, {%0,%1,%2,%3};"
        : "+f"(c[0]), "+f"(c[1]), "+f"(c[2]), "+f"(c[3])
        : "r"(A[0]), "r"(A[1]), "r"(A[2]), "r"(A[3]), "r"(Bp[0]), "r"(Bp[1]));
}

enum { EPI_QKV3 = 0, EPI_SCORES = 1, EPI_RND = 2, EPI_BIASRES = 3, EPI_GELU = 4 };

// ===========================================================================
// gemm_big: C[M,N] = A[M,K] @ Wpacked^T, fused epilogue.
// CTA 128 x (NT*32) x 32, 8 warps (2M x 4N), warp tile 64 x (NT*8).
// NT=8 -> TBN=256 (QKV, W1). NT=4 -> TBN=128 (Wo, W2: better wave count).
// A: K-major, smem stride 36 (conflict-free fragment loads).
// B: fragment-packed global layout with baked-in bank swizzle:
//   element (n,k): g=n&7, n8=n>>3, kt=k>>5, ks=(k>>3)&3, h=(k>>2)&1, t=k&3
//   off = (((kt*NB8tot + n8)*32 + g*4+t)*8) + ((ks*2 + h) ^ ((g&3)<<1))
// smem copy purely linear; LDS.64 B reads fully conflict-free.
// Register double-buffered fragments; 4-stage cp.async pipeline.
// ===========================================================================
#define GB_AS 36
#define GB_A_FLOATS (128*GB_AS)                 // 4608 per stage
#define GB_STAGES 4

template<int EPI, int NT>
__global__ void __launch_bounds__(256, 1) gemm_big(
    const float* __restrict__ A, const float* __restrict__ Bp,
    float* __restrict__ C0, float* __restrict__ C1, float* __restrict__ C2,
    int K, int NB8tot, int ldc,
    const float* __restrict__ bias0, const float* __restrict__ bias1,
    const float* __restrict__ bias2, const float* __restrict__ extra, float scale)
{
    constexpr int BF = NT * 1024;               // B floats per stage
    extern __shared__ float sm[];
    float* sA = sm;
    float* sB = sm + GB_STAGES * GB_A_FLOATS;

    const int tid = threadIdx.x;
    const int ntk = K >> 5;

    const float* Ab = A + (long)blockIdx.y * 128 * K;
    const long bslice = (long)blockIdx.x * NT * 1024;  // CTA n8 window in a ktile slab

    auto issue = [&](int kt, int stg) {
        float* sa = sA + stg * GB_A_FLOATS;
        const float* ag = Ab + (long)kt * 32;
#pragma unroll
        for (int i = 0; i < 4; i++) {
            int c = tid + i * 256;                 // 0..1023 chunks of A tile
            int r = c >> 3, cc = (c & 7) * 4;
            cpa16(sa + r * GB_AS + cc, ag + (long)r * K + cc);
        }
        float* sb = sB + stg * BF;
        const float* bg = Bp + (long)kt * NB8tot * 256 + bslice;
#pragma unroll
        for (int i = 0; i < NT; i++) {
            int c = tid + i * 256;                 // linear copy
            cpa16(sb + c * 4, bg + (long)c * 4);
        }
    };

    const int warp = tid >> 5, lane = tid & 31;
    const int wm = (warp & 1) * 64;       // 2 warps along M
    const int wnidx = warp >> 1;          // 4 warps along N
    const int g = lane >> 2, t = lane & 3;
    const int bswz = (g & 3) << 1;        // ks-permutation baked into packed layout

    float acc[4][NT][4];
#pragma unroll
    for (int mt = 0; mt < 4; mt++)
#pragma unroll
        for (int nt = 0; nt < NT; nt++)
#pragma unroll
            for (int i = 0; i < 4; i++) acc[mt][nt][i] = 0.f;

    issue(0, 0); cp_commit();
    issue(1, 1); cp_commit();
    issue(2, 2); cp_commit();

    for (int it = 0; it < ntk; ++it) {
        const int stg = it & 3;
        if (it + 3 < ntk) issue(it + 3, (it + 3) & 3);
        cp_commit();
        cp_wait3();
        __syncthreads();

        const float* sa  = sA + stg * GB_A_FLOATS;
        const float* sbw = sB + stg * BF + wnidx * (NT * 256) + lane * 8;

        float af[2][4][4];
        float bf[2][NT][2];

        // prime ks=0 fragments
#pragma unroll
        for (int mt = 0; mt < 4; mt++) {
            const int r0 = wm + mt * 16 + g;
            af[0][mt][0] = sa[r0 * GB_AS + t];
            af[0][mt][1] = sa[(r0 + 8) * GB_AS + t];
            af[0][mt][2] = sa[r0 * GB_AS + t + 4];
            af[0][mt][3] = sa[(r0 + 8) * GB_AS + t + 4];
        }
#pragma unroll
        for (int nt = 0; nt < NT; nt++) {
            float2 b = *(const float2*)(sbw + nt * 256 + (0 ^ bswz));
            bf[0][nt][0] = b.x; bf[0][nt][1] = b.y;
        }

#pragma unroll
        for (int ks = 0; ks < 4; ks++) {
            const int cur = ks & 1, nxt = cur ^ 1;
            if (ks < 3) {
                const int k0 = (ks + 1) * 8;
#pragma unroll
                for (int mt = 0; mt < 4; mt++) {
                    const int r0 = wm + mt * 16 + g;
                    af[nxt][mt][0] = sa[r0 * GB_AS + k0 + t];
                    af[nxt][mt][1] = sa[(r0 + 8) * GB_AS + k0 + t];
                    af[nxt][mt][2] = sa[r0 * GB_AS + k0 + t + 4];
                    af[nxt][mt][3] = sa[(r0 + 8) * GB_AS + k0 + t + 4];
                }
                const int bo = ((ks + 1) * 2) ^ bswz;
#pragma unroll
                for (int nt = 0; nt < NT; nt++) {
                    float2 b = *(const float2*)(sbw + nt * 256 + bo);
                    bf[nxt][nt][0] = b.x; bf[nxt][nt][1] = b.y;
                }
            }
#pragma unroll
            for (int mt = 0; mt < 4; mt++)
#pragma unroll
                for (int nt = 0; nt < NT; nt++)
                    mma_tf32(acc[mt][nt], af[cur][mt], bf[cur][nt]);
        }
        __syncthreads();
    }

    // ---------------- epilogue ----------------
    const int wn = wnidx * (NT * 8);
    const int nbase = blockIdx.x * (NT * 32);
    const int mbase = blockIdx.y * 128 + wm;

    float* dst = C0;
    const float* bs = bias0;
    float sc = scale;
    int nloc = nbase;
    if (EPI == EPI_QKV3) {
        const int seg = nbase >> 11;              // CTA fully inside one of q/k/v
        nloc = nbase & 2047;
        if (seg == 1) { dst = C1; bs = bias1; sc = 1.0f; }
        else if (seg == 2) { dst = C2; bs = bias2; sc = 1.0f; }
    }

#pragma unroll
    for (int mt = 0; mt < 4; mt++) {
#pragma unroll
        for (int half = 0; half < 2; half++) {
            const int row = mbase + mt * 16 + g + half * 8;
            const long crow = (long)row * ldc;
#pragma unroll
            for (int nt = 0; nt < NT; nt++) {
                const int cc = wn + nt * 8 + 2 * t;
                const int col = nloc + cc;
                float v0 = acc[mt][nt][half * 2 + 0];
                float v1 = acc[mt][nt][half * 2 + 1];
                if (EPI == EPI_QKV3) {
                    v0 = to_tf32((v0 + bs[col]) * sc);
                    v1 = to_tf32((v1 + bs[col + 1]) * sc);
                } else if (EPI == EPI_BIASRES) {
                    v0 += bs[col]     + extra[crow + col];
                    v1 += bs[col + 1] + extra[crow + col + 1];
                } else if (EPI == EPI_GELU) {
                    v0 += bs[col];
                    v1 += bs[col + 1];
                    v0 = to_tf32(0.5f * v0 * (1.f + erff(v0 * 0.7071067811865476f)));
                    v1 = to_tf32(0.5f * v1 * (1.f + erff(v1 * 0.7071067811865476f)));
                }
                *(float2*)(dst + crow + col) = make_float2(v0, v1);
            }
        }
    }
}

// ===========================================================================
// SIMT GEMM for attention (scores QK^T and P@V) — unchanged (proven)
// ===========================================================================
#define SA_STRIDE 36
#define SBNN_STRIDE 136
#define SA_ELEMS (128*SA_STRIDE)
#define SBKM_ELEMS (128*SA_STRIDE)
#define SBNN_ELEMS (32*SBNN_STRIDE)

template<bool BKM, int EPI>
__global__ void __launch_bounds__(256, 1) gemm_k(
    const float* __restrict__ A, const float* __restrict__ Bm, float* __restrict__ C,
    int lda, int ldb, int ldc, int ntk,
    long aB, long aH, long bB, long bH, long cB, long cH, long eB, long eH, int Hdiv,
    const float* __restrict__ bias, const float* __restrict__ extra, float scale)
{
    extern __shared__ float sm[];
    float* sA = sm;
    float* sB = sm + 3 * SA_ELEMS;

    const int tid = threadIdx.x;
    const int z = blockIdx.z;
    const int bz = z / Hdiv, hz = z - bz * Hdiv;

    const float* Ag = A + bz * aB + hz * aH + (long)(blockIdx.y * 128) * lda;
    const float* Bg;
    if (BKM) Bg = Bm + bz * bB + hz * bH + (long)(blockIdx.x * 128) * ldb;
    else     Bg = Bm + bz * bB + hz * bH + blockIdx.x * 128;

    const int ar = tid >> 3, ac = (tid & 7) * 4;
    const int br = BKM ? (tid >> 3) : (tid >> 5);
    const int bc = BKM ? ((tid & 7) * 4) : ((tid & 31) * 4);

    auto issue = [&](int kt, int stg) {
        const float* a0 = Ag + (long)kt * 32 + ac;
        float* sa = sA + stg * SA_ELEMS;
#pragma unroll
        for (int p = 0; p < 4; p++)
            cpa16(sa + (ar + p * 32) * SA_STRIDE + ac, a0 + (long)(ar + p * 32) * lda);
        if (BKM) {
            const float* b0 = Bg + (long)kt * 32 + bc;
            float* sb = sB + stg * SBKM_ELEMS;
#pragma unroll
            for (int p = 0; p < 4; p++)
                cpa16(sb + (br + p * 32) * SA_STRIDE + bc, b0 + (long)(br + p * 32) * ldb);
        } else {
            const float* b0 = Bg + (long)kt * 32 * ldb + bc;
            float* sb = sB + stg * SBNN_ELEMS;
#pragma unroll
            for (int p = 0; p < 4; p++)
                cpa16(sb + (br + p * 8) * SBNN_STRIDE + bc, b0 + (long)(br + p * 8) * ldb);
        }
    };

    const int warp = tid >> 5, lane = tid & 31;
    const int wm = (warp & 3) * 32;
    const int wn = (warp >> 2) * 64;
    const int g = lane >> 2, t = lane & 3;

    float acc[2][8][4];
#pragma unroll
    for (int mt = 0; mt < 2; mt++)
#pragma unroll
        for (int nt = 0; nt < 8; nt++)
#pragma unroll
            for (int i = 0; i < 4; i++) acc[mt][nt][i] = 0.f;

    issue(0, 0); cp_commit();
    issue(1, 1); cp_commit();

    for (int it = 0; it < ntk; ++it) {
        int stg = it % 3;
        if (it + 2 < ntk) issue(it + 2, (it + 2) % 3);
        cp_commit();
        cp_wait2();
        __syncthreads();

        const float* sa = sA + stg * SA_ELEMS;
        const float* sb = sB + stg * (BKM ? SBKM_ELEMS : SBNN_ELEMS);
#pragma unroll
        for (int ks = 0; ks < 4; ks++) {
            const int k0 = ks * 8;
            float af[2][4];
#pragma unroll
            for (int mt = 0; mt < 2; mt++) {
                int r0 = wm + mt * 16 + g;
                af[mt][0] = sa[r0 * SA_STRIDE + k0 + t];
                af[mt][1] = sa[(r0 + 8) * SA_STRIDE + k0 + t];
                af[mt][2] = sa[r0 * SA_STRIDE + k0 + t + 4];
                af[mt][3] = sa[(r0 + 8) * SA_STRIDE + k0 + t + 4];
            }
            float bf[8][2];
#pragma unroll
            for (int nt = 0; nt < 8; nt++) {
                int c0 = wn + nt * 8 + g;
                if (BKM) {
                    bf[nt][0] = sb[c0 * SA_STRIDE + k0 + t];
                    bf[nt][1] = sb[c0 * SA_STRIDE + k0 + t + 4];
                } else {
                    bf[nt][0] = sb[(k0 + t) * SBNN_STRIDE + c0];
                    bf[nt][1] = sb[(k0 + t + 4) * SBNN_STRIDE + c0];
                }
            }
#pragma unroll
            for (int mt = 0; mt < 2; mt++)
#pragma unroll
                for (int nt = 0; nt < 8; nt++)
                    mma_tf32(acc[mt][nt], af[mt], bf[nt]);
        }
        __syncthreads();
    }

    const long co = bz * cB + hz * cH;
    const long eo = bz * eB + hz * eH;
    const int mbase = blockIdx.y * 128 + wm;
    const int nbase = blockIdx.x * 128 + wn;

#pragma unroll
    for (int mt = 0; mt < 2; mt++) {
#pragma unroll
        for (int half = 0; half < 2; half++) {
            const int row = mbase + mt * 16 + g + half * 8;
#pragma unroll
            for (int nt = 0; nt < 8; nt++) {
                const int col = nbase + nt * 8 + 2 * t;
                float v0 = acc[mt][nt][half * 2 + 0];
                float v1 = acc[mt][nt][half * 2 + 1];
                if (EPI == EPI_SCORES) {
                    if (extra[eo + col]     == 0.f) v0 += -3.4028234663852886e38f;
                    if (extra[eo + col + 1] == 0.f) v1 += -3.4028234663852886e38f;
                } else if (EPI == EPI_RND) {
                    v0 = to_tf32(v0);
                    v1 = to_tf32(v1);
                }
                *(float2*)(C + co + (long)row * ldc + col) = make_float2(v0, v1);
            }
        }
    }
}

// ---------------------------------------------------------------------------
// LayerNorm (tf32-rna rounded output)
// ---------------------------------------------------------------------------
__global__ void ln_kernel(const float* __restrict__ x, const float* __restrict__ w,
                          const float* __restrict__ b, float* __restrict__ out)
{
    __shared__ float s1[8], s2[8];
    const int row = blockIdx.x, tid = threadIdx.x;
    const int lane = tid & 31, wid = tid >> 5;
    const float4* xr = (const float4*)(x + (long)row * DD);
    float4 v0 = xr[tid], v1 = xr[tid + 256];

    float s = v0.x + v0.y + v0.z + v0.w + v1.x + v1.y + v1.z + v1.w;
    float q = v0.x*v0.x + v0.y*v0.y + v0.z*v0.z + v0.w*v0.w
            + v1.x*v1.x + v1.y*v1.y + v1.z*v1.z + v1.w*v1.w;
#pragma unroll
    for (int o = 16; o; o >>= 1) {
        s += __shfl_xor_sync(0xffffffffu, s, o);
        q += __shfl_xor_sync(0xffffffffu, q, o);
    }
    if (lane == 0) { s1[wid] = s; s2[wid] = q; }
    __syncthreads();
    if (tid < 8) {
        s = s1[tid]; q = s2[tid];
#pragma unroll
        for (int o = 4; o; o >>= 1) {
            s += __shfl_xor_sync(0xffu, s, o);
            q += __shfl_xor_sync(0xffu, q, o);
        }
        if (tid == 0) { s1[0] = s; s2[0] = q; }
    }
    __syncthreads();
    const float mu = s1[0] * (1.f / DD);
    const float var = s2[0] * (1.f / DD) - mu * mu;
    const float r = rsqrtf(var + 1e-5f);

    float4 o0, o1;
    int c0 = tid * 4, c1 = (tid + 256) * 4;
    o0.x = to_tf32((v0.x - mu) * r * w[c0+0] + b[c0+0]);
    o0.y = to_tf32((v0.y - mu) * r * w[c0+1] + b[c0+1]);
    o0.z = to_tf32((v0.z - mu) * r * w[c0+2] + b[c0+2]);
    o0.w = to_tf32((v0.w - mu) * r * w[c0+3] + b[c0+3]);
    o1.x = to_tf32((v1.x - mu) * r * w[c1+0] + b[c1+0]);
    o1.y = to_tf32((v1.y - mu) * r * w[c1+1] + b[c1+1]);
    o1.z = to_tf32((v1.z - mu) * r * w[c1+2] + b[c1+2]);
    o1.w = to_tf32((v1.w - mu) * r * w[c1+3] + b[c1+3]);
    float4* orow = (float4*)(out + (long)row * DD);
    orow[tid] = o0; orow[tid + 256] = o1;
}

// ---------------------------------------------------------------------------
// Softmax (tf32-rna rounded probs)
// ---------------------------------------------------------------------------
__global__ void softmax_kernel(float* __restrict__ sc)
{
    __shared__ float red[8];
    const long row = blockIdx.x;
    float4* p = (float4*)(sc + row * (long)SS);
    const int tid = threadIdx.x, lane = tid & 31, wid = tid >> 5;
    float4 v = p[tid];

    float m = fmaxf(fmaxf(v.x, v.y), fmaxf(v.z, v.w));
#pragma unroll
    for (int o = 16; o; o >>= 1) m = fmaxf(m, __shfl_xor_sync(0xffffffffu, m, o));
    if (lane == 0) red[wid] = m;
    __syncthreads();
    if (tid < 8) {
        m = red[tid];
#pragma unroll
        for (int o = 4; o; o >>= 1) m = fmaxf(m, __shfl_xor_sync(0xffu, m, o));
        if (tid == 0) red[0] = m;
    }
    __syncthreads();
    const float M = red[0];
    __syncthreads();

    v.x = expf(v.x - M); v.y = expf(v.y - M);
    v.z = expf(v.z - M); v.w = expf(v.w - M);
    float s = v.x + v.y + v.z + v.w;
#pragma unroll
    for (int o = 16; o; o >>= 1) s += __shfl_xor_sync(0xffffffffu, s, o);
    if (lane == 0) red[wid] = s;
    __syncthreads();
    if (tid < 8) {
        s = red[tid];
#pragma unroll
        for (int o = 4; o; o >>= 1) s += __shfl_xor_sync(0xffu, s, o);
        if (tid == 0) red[0] = s;
    }
    __syncthreads();
    const float inv = 1.f / red[0];
    v.x = to_tf32(v.x * inv); v.y = to_tf32(v.y * inv);
    v.z = to_tf32(v.z * inv); v.w = to_tf32(v.w * inv);
    p[tid] = v;
}

// ---------------------------------------------------------------------------
// Round+pack weights (split into 2 launches so QKV gemm is our launch #4,
// which is the launch ncu profiles).
// ---------------------------------------------------------------------------
__device__ __forceinline__ void pack4(const float* __restrict__ src, float* __restrict__ dst,
                                      int K, int NB8tot, int n8off, long s)
{
    const int kq = K >> 2;
    const int n = (int)(s / kq);
    const int k4 = (int)(s - (long)n * kq);
    float4 v = ((const float4*)src)[s];
    float vals[4];
    vals[0] = to_tf32(v.x); vals[1] = to_tf32(v.y);
    vals[2] = to_tf32(v.z); vals[3] = to_tf32(v.w);
    const int gg = n & 7;
    const long n8 = (n >> 3) + n8off;
    const int swz = (gg & 3) << 1;
#pragma unroll
    for (int c = 0; c < 4; c++) {
        const int k = k4 * 4 + c;
        const int kt = k >> 5, ks = (k >> 3) & 3, h = (k >> 2) & 1, t = k & 3;
        const long base = (((long)kt * NB8tot + n8) * 32 + (gg * 4 + t)) * 8;
        dst[base + ((ks * 2 + h) ^ swz)] = vals[c];
    }
}

__global__ void pack_attn(
    const float* __restrict__ Wq, const float* __restrict__ Wk,
    const float* __restrict__ Wv, const float* __restrict__ Wo,
    float* __restrict__ dqkv, float* __restrict__ dwo)
{
    const long M1 = 1048576;
    const long i = (long)blockIdx.x * 256 + threadIdx.x;
    if      (i < 1*M1) pack4(Wq, dqkv, DD, 768, 0,   i);
    else if (i < 2*M1) pack4(Wk, dqkv, DD, 768, 256, i - 1*M1);
    else if (i < 3*M1) pack4(Wv, dqkv, DD, 768, 512, i - 2*M1);
    else               pack4(Wo, dwo,  DD, 256, 0,   i - 3*M1);
}

__global__ void pack_mlp(
    const float* __restrict__ W1, const float* __restrict__ W2,
    float* __restrict__ dw1, float* __restrict__ dw2)
{
    const long M4 = 4194304;
    const long i = (long)blockIdx.x * 256 + threadIdx.x;
    if (i < M4) pack4(W1, dw1, DD, 1024, 0, i);
    else        pack4(W2, dw2, II, 256, 0,  i - M4);
}

// ---------------------------------------------------------------------------
// Host launch
// ---------------------------------------------------------------------------
static const int SMEM_KM = 3 * (SA_ELEMS + SBKM_ELEMS) * 4;
static const int SMEM_NN = 3 * (SA_ELEMS + SBNN_ELEMS) * 4;
static const int GB_SMEM8 = GB_STAGES * (GB_A_FLOATS + 8*1024) * 4;  // 204800
static const int GB_SMEM4 = GB_STAGES * (GB_A_FLOATS + 4*1024) * 4;  // 139264

extern "C" void kernel_launch(void* const* d_in, const int* in_sizes, int n_in,
                              void* d_out, int out_size)
{
    const float* hid   = (const float*)d_in[1];
    const float* amask = (const float*)d_in[2];
    const float* Wq = (const float*)d_in[4];  const float* bq = (const float*)d_in[5];
    const float* Wk = (const float*)d_in[6];  const float* bk = (const float*)d_in[7];
    const float* Wv = (const float*)d_in[8];  const float* bv = (const float*)d_in[9];
    const float* Wo = (const float*)d_in[10]; const float* bo = (const float*)d_in[11];
    const float* l1w = (const float*)d_in[12]; const float* l1b = (const float*)d_in[13];
    const float* l2w = (const float*)d_in[14]; const float* l2b = (const float*)d_in[15];
    const float* W1 = (const float*)d_in[16]; const float* b1 = (const float*)d_in[17];
    const float* W2 = (const float*)d_in[18]; const float* b2 = (const float*)d_in[19];
    float* out = (float*)d_out;

    void* p;
    cudaGetSymbolAddress(&p, g_xln1);  float* xln1 = (float*)p;
    cudaGetSymbolAddress(&p, g_q);     float* q    = (float*)p;
    cudaGetSymbolAddress(&p, g_k);     float* k    = (float*)p;
    cudaGetSymbolAddress(&p, g_v);     float* v    = (float*)p;
    cudaGetSymbolAddress(&p, g_scores);float* sc   = (float*)p;
    cudaGetSymbolAddress(&p, g_attn);  float* attn = (float*)p;
    cudaGetSymbolAddress(&p, g_hidden);float* hd2  = (float*)p;
    cudaGetSymbolAddress(&p, g_yln2);  float* yln2 = (float*)p;
    cudaGetSymbolAddress(&p, g_mid);   float* mid  = (float*)p;
    cudaGetSymbolAddress(&p, g_wqkv);  float* wqkv = (float*)p;
    cudaGetSymbolAddress(&p, g_wo);    float* wo   = (float*)p;
    cudaGetSymbolAddress(&p, g_w1);    float* w1   = (float*)p;
    cudaGetSymbolAddress(&p, g_w2);    float* w2   = (float*)p;

    cudaFuncSetAttribute((const void*)gemm_big<EPI_QKV3,8>,   cudaFuncAttributeMaxDynamicSharedMemorySize, GB_SMEM8);
    cudaFuncSetAttribute((const void*)gemm_big<EPI_GELU,8>,   cudaFuncAttributeMaxDynamicSharedMemorySize, GB_SMEM8);
    cudaFuncSetAttribute((const void*)gemm_big<EPI_BIASRES,4>,cudaFuncAttributeMaxDynamicSharedMemorySize, GB_SMEM4);
    cudaFuncSetAttribute((const void*)gemm_k<true,  EPI_SCORES>, cudaFuncAttributeMaxDynamicSharedMemorySize, SMEM_KM);
    cudaFuncSetAttribute((const void*)gemm_k<false, EPI_RND>,    cudaFuncAttributeMaxDynamicSharedMemorySize, SMEM_NN);

    const float qscale = 0.08838834764831845f;  // 128^-0.5

    // 1) pack attn weights (4M float4)
    pack_attn<<<16384, 256>>>(Wq, Wk, Wv, Wo, wqkv, wo);
    // 2) pack mlp weights (8M float4)
    pack_mlp<<<32768, 256>>>(W1, W2, w1, w2);
    // 3) LN1
    ln_kernel<<<MTOK, 256>>>(hid, l1w, l1b, xln1);
    // 4) fused QKV projection [4096 x 6144]  <-- ncu profiles this launch
    gemm_big<EPI_QKV3,8><<<dim3(24, 32), 256, GB_SMEM8>>>(
        xln1, wqkv, q, k, v, DD, 768, DD, bq, bk, bv, nullptr, qscale);

    // 5) scores = q @ k^T (+mask)
    gemm_k<true, EPI_SCORES><<<dim3(8, 8, BB*HH), 256, SMEM_KM>>>(
        q, k, sc, DD, DD, SS, 4,
        (long)SS*DD, HDIM, (long)SS*DD, HDIM,
        (long)HH*SS*SS, (long)SS*SS, (long)SS, 0, HH,
        nullptr, amask, 1.0f);

    // 6) softmax
    softmax_kernel<<<BB*HH*SS, 256>>>(sc);

    // 7) attn = P @ V
    gemm_k<false, EPI_RND><<<dim3(1, 8, BB*HH), 256, SMEM_NN>>>(
        sc, v, attn, SS, DD, DD, 32,
        (long)HH*SS*SS, (long)SS*SS, (long)SS*DD, HDIM,
        (long)SS*DD, HDIM, 0, 0, HH,
        nullptr, nullptr, 1.0f);

    // 8) hidden = residual + attn @ Wo^T + bo  (TBN=128: 512 CTAs, 3.46 waves)
    gemm_big<EPI_BIASRES,4><<<dim3(16, 32), 256, GB_SMEM4>>>(
        attn, wo, hd2, nullptr, nullptr, DD, 256, DD, bo, nullptr, nullptr, hid, 1.0f);

    // 9) LN2
    ln_kernel<<<MTOK, 256>>>(hd2, l2w, l2b, yln2);

    // 10) mid = gelu(yln2 @ W1^T + b1)
    gemm_big<EPI_GELU,8><<<dim3(32, 32), 256, GB_SMEM8>>>(
        yln2, w1, mid, nullptr, nullptr, DD, 1024, II, b1, nullptr, nullptr, nullptr, 1.0f);

    // 11) out = hidden + mid @ W2^T + b2 (K=8192, TBN=128: 512 CTAs)
    gemm_big<EPI_BIASRES,4><<<dim3(16, 32), 256, GB_SMEM4>>>(
        mid, w2, out, nullptr, nullptr, II, 256, DD, b2, nullptr, nullptr, hd2, 1.0f);
}

// round 9
// speedup vs baseline: 1.0181x; 1.0181x over previous
#include <cuda_runtime.h>
#include <cstdint>
#include <cmath>

// ---------------------------------------------------------------------------
// Problem constants
// ---------------------------------------------------------------------------
#define BB 4
#define SS 1024
#define DD 2048
#define HH 16
#define HDIM 128
#define II 8192
#define MTOK (BB*SS)

// ---------------------------------------------------------------------------
// Scratch
// ---------------------------------------------------------------------------
__device__ __align__(256) float g_xln1 [MTOK*DD];
__device__ __align__(256) float g_q    [MTOK*DD];
__device__ __align__(256) float g_k    [MTOK*DD];
__device__ __align__(256) float g_v    [MTOK*DD];
__device__ __align__(256) float g_scores[(long)BB*HH*SS*SS];
__device__ __align__(256) float g_attn [MTOK*DD];
__device__ __align__(256) float g_hidden[MTOK*DD];
__device__ __align__(256) float g_yln2 [MTOK*DD];
__device__ __align__(256) float g_mid  [MTOK*II];
__device__ __align__(256) float g_wqkv[3*DD*DD];   // packed fragments, N=6144 (NB8=768)
__device__ __align__(256) float g_wo[DD*DD];       // packed, NB8=256
__device__ __align__(256) float g_w1[II*DD];       // packed, NB8=1024, K=2048
__device__ __align__(256) float g_w2[DD*II];       // packed, NB8=256,  K=8192

// ---------------------------------------------------------------------------
// Helpers
// ---------------------------------------------------------------------------
__device__ __forceinline__ float to_tf32(float x) {
    float r;
    asm("cvt.rna.tf32.f32 %0, %1;" : "=f"(r) : "f"(x));
    return r;
}
__device__ __forceinline__ void cpa16(void* sdst, const void* gsrc) {
    uint32_t s = (uint32_t)__cvta_generic_to_shared(sdst);
    asm volatile("cp.async.cg.shared.global [%0], [%1], 16;" :: "r"(s), "l"(gsrc));
}
__device__ __forceinline__ void cp_commit() { asm volatile("cp.async.commit_group;"); }
__device__ __forceinline__ void cp_wait2()  { asm volatile("cp.async.wait_group 2;"); }

__device__ __forceinline__ void mma_tf32(float c[4], const float a[4], const float b[2]) {
    const uint32_t* A = reinterpret_cast<const uint32_t*>(a);
    const uint32_t* Bp = reinterpret_cast<const uint32_t*>(b);
    asm volatile(
        "mma.sync.aligned.m16n8k8.row.col.f32.tf32.tf32.f32 "
        "{%0,%1,%2,%3}, {%4,%5,%6,%7}, {%8,%9}, {%0,%1,%2,%3};"
        : "+f"(c[0]), "+f"(c[1]), "+f"(c[2]), "+f"(c[3])
        : "r"(A[0]), "r"(A[1]), "r"(A[2]), "r"(A[3]), "r"(Bp[0]), "r"(Bp[1]));
}

enum { EPI_QKV3 = 0, EPI_SCORES = 1, EPI_RND = 2, EPI_BIASRES = 3, EPI_GELU = 4 };

// ===========================================================================
// gemm_big: C[M,N] = A[M,K] @ Wpacked^T, fused epilogue.
// CTA 128x256x32, **512 threads / 16 warps** (4M x 4N), warp tile 32x64.
// acc[2][8][4] = 64 regs -> ~120 regs/thread -> 4 warps/SMSP (latency fix).
// A: K-major, smem stride 36. B: fragment-packed global layout w/ baked swizzle:
//   element (n,k): g=n&7, n8=n>>3, kt=k>>5, ks=(k>>3)&3, h=(k>>2)&1, t=k&3
//   off = (((kt*NB8tot + n8)*32 + g*4+t)*8) + ((ks*2 + h) ^ ((g&3)<<1))
// B LDS.64 fully conflict-free; af single-buffered, bf double-buffered.
// 3-stage cp.async pipeline (R6-proven).
// ===========================================================================
#define GB_AS 36
#define GB_A_FLOATS (128*GB_AS)                  // 4608 per stage
#define GB_B_FLOATS 8192                          // 256x32 per stage
#define GB_SMEM (3*(GB_A_FLOATS+GB_B_FLOATS)*4)  // 153600 bytes

template<int EPI>
__global__ void __launch_bounds__(512, 1) gemm_big(
    const float* __restrict__ A, const float* __restrict__ Bp,
    float* __restrict__ C0, float* __restrict__ C1, float* __restrict__ C2,
    int K, int NB8tot, int ldc,
    const float* __restrict__ bias0, const float* __restrict__ bias1,
    const float* __restrict__ bias2, const float* __restrict__ extra, float scale)
{
    extern __shared__ float sm[];
    float* sA = sm;
    float* sB = sm + 3 * GB_A_FLOATS;

    const int tid = threadIdx.x;
    const int ntk = K >> 5;

    const float* Ab = A + (long)blockIdx.y * 128 * K;
    const long bslice = (long)blockIdx.x * 8192;   // CTA n8 window in a ktile slab

    auto issue = [&](int kt, int stg) {
        float* sa = sA + stg * GB_A_FLOATS;
        const float* ag = Ab + (long)kt * 32;
#pragma unroll
        for (int i = 0; i < 2; i++) {
            int c = tid + i * 512;                 // 0..1023 chunks of A tile
            int r = c >> 3, cc = (c & 7) * 4;
            cpa16(sa + r * GB_AS + cc, ag + (long)r * K + cc);
        }
        float* sb = sB + stg * GB_B_FLOATS;
        const float* bg = Bp + (long)kt * NB8tot * 256 + bslice;
#pragma unroll
        for (int i = 0; i < 4; i++) {
            int c = tid + i * 512;                 // 0..2047: pure linear copy
            cpa16(sb + c * 4, bg + (long)c * 4);
        }
    };

    const int warp = tid >> 5, lane = tid & 31;
    const int wm = (warp & 3) * 32;       // 4 warps along M
    const int wnidx = warp >> 2;          // 4 warps along N (64 cols each)
    const int g = lane >> 2, t = lane & 3;
    const int bswz = (g & 3) << 1;        // baked bank-swizzle offset

    float acc[2][8][4];
#pragma unroll
    for (int mt = 0; mt < 2; mt++)
#pragma unroll
        for (int nt = 0; nt < 8; nt++)
#pragma unroll
            for (int i = 0; i < 4; i++) acc[mt][nt][i] = 0.f;

    issue(0, 0); cp_commit();
    issue(1, 1); cp_commit();

    for (int it = 0; it < ntk; ++it) {
        const int stg = it % 3;
        if (it + 2 < ntk) issue(it + 2, (it + 2) % 3);
        cp_commit();
        cp_wait2();
        __syncthreads();

        const float* sa  = sA + stg * GB_A_FLOATS;
        const float* sbw = sB + stg * GB_B_FLOATS + wnidx * 2048 + lane * 8;

        float bf[2][8][2];
        // prime bf ks=0
#pragma unroll
        for (int nt = 0; nt < 8; nt++) {
            float2 b = *(const float2*)(sbw + nt * 256 + bswz);
            bf[0][nt][0] = b.x; bf[0][nt][1] = b.y;
        }

#pragma unroll
        for (int ks = 0; ks < 4; ks++) {
            const int cur = ks & 1, nxt = cur ^ 1;
            const int k0 = ks * 8;
            float af[2][4];
#pragma unroll
            for (int mt = 0; mt < 2; mt++) {
                const int r0 = wm + mt * 16 + g;
                af[mt][0] = sa[r0 * GB_AS + k0 + t];
                af[mt][1] = sa[(r0 + 8) * GB_AS + k0 + t];
                af[mt][2] = sa[r0 * GB_AS + k0 + t + 4];
                af[mt][3] = sa[(r0 + 8) * GB_AS + k0 + t + 4];
            }
            if (ks < 3) {
                const int bo = ((ks + 1) * 2) ^ bswz;
#pragma unroll
                for (int nt = 0; nt < 8; nt++) {
                    float2 b = *(const float2*)(sbw + nt * 256 + bo);
                    bf[nxt][nt][0] = b.x; bf[nxt][nt][1] = b.y;
                }
            }
#pragma unroll
            for (int mt = 0; mt < 2; mt++)
#pragma unroll
                for (int nt = 0; nt < 8; nt++)
                    mma_tf32(acc[mt][nt], af[mt], bf[cur][nt]);
        }
        __syncthreads();
    }

    // ---------------- epilogue ----------------
    const int wn = wnidx * 64;
    const int nbase = blockIdx.x * 256;
    const int mbase = blockIdx.y * 128 + wm;

    float* dst = C0;
    const float* bs = bias0;
    float sc = scale;
    int nloc = nbase;
    if (EPI == EPI_QKV3) {
        const int seg = nbase >> 11;              // CTA fully inside one of q/k/v
        nloc = nbase & 2047;
        if (seg == 1) { dst = C1; bs = bias1; sc = 1.0f; }
        else if (seg == 2) { dst = C2; bs = bias2; sc = 1.0f; }
    }

#pragma unroll
    for (int mt = 0; mt < 2; mt++) {
#pragma unroll
        for (int half = 0; half < 2; half++) {
            const int row = mbase + mt * 16 + g + half * 8;
            const long crow = (long)row * ldc;
#pragma unroll
            for (int nt = 0; nt < 8; nt++) {
                const int cc = wn + nt * 8 + 2 * t;
                const int col = nloc + cc;
                float v0 = acc[mt][nt][half * 2 + 0];
                float v1 = acc[mt][nt][half * 2 + 1];
                if (EPI == EPI_QKV3) {
                    v0 = to_tf32((v0 + bs[col]) * sc);
                    v1 = to_tf32((v1 + bs[col + 1]) * sc);
                } else if (EPI == EPI_BIASRES) {
                    v0 += bs[col]     + extra[crow + col];
                    v1 += bs[col + 1] + extra[crow + col + 1];
                } else if (EPI == EPI_GELU) {
                    v0 += bs[col];
                    v1 += bs[col + 1];
                    v0 = to_tf32(0.5f * v0 * (1.f + erff(v0 * 0.7071067811865476f)));
                    v1 = to_tf32(0.5f * v1 * (1.f + erff(v1 * 0.7071067811865476f)));
                }
                *(float2*)(dst + crow + col) = make_float2(v0, v1);
            }
        }
    }
}

// ===========================================================================
// SIMT GEMM for attention (scores QK^T and P@V) — unchanged (proven)
// ===========================================================================
#define SA_STRIDE 36
#define SBNN_STRIDE 136
#define SA_ELEMS (128*SA_STRIDE)
#define SBKM_ELEMS (128*SA_STRIDE)
#define SBNN_ELEMS (32*SBNN_STRIDE)

template<bool BKM, int EPI>
__global__ void __launch_bounds__(256, 1) gemm_k(
    const float* __restrict__ A, const float* __restrict__ Bm, float* __restrict__ C,
    int lda, int ldb, int ldc, int ntk,
    long aB, long aH, long bB, long bH, long cB, long cH, long eB, long eH, int Hdiv,
    const float* __restrict__ bias, const float* __restrict__ extra, float scale)
{
    extern __shared__ float sm[];
    float* sA = sm;
    float* sB = sm + 3 * SA_ELEMS;

    const int tid = threadIdx.x;
    const int z = blockIdx.z;
    const int bz = z / Hdiv, hz = z - bz * Hdiv;

    const float* Ag = A + bz * aB + hz * aH + (long)(blockIdx.y * 128) * lda;
    const float* Bg;
    if (BKM) Bg = Bm + bz * bB + hz * bH + (long)(blockIdx.x * 128) * ldb;
    else     Bg = Bm + bz * bB + hz * bH + blockIdx.x * 128;

    const int ar = tid >> 3, ac = (tid & 7) * 4;
    const int br = BKM ? (tid >> 3) : (tid >> 5);
    const int bc = BKM ? ((tid & 7) * 4) : ((tid & 31) * 4);

    auto issue = [&](int kt, int stg) {
        const float* a0 = Ag + (long)kt * 32 + ac;
        float* sa = sA + stg * SA_ELEMS;
#pragma unroll
        for (int p = 0; p < 4; p++)
            cpa16(sa + (ar + p * 32) * SA_STRIDE + ac, a0 + (long)(ar + p * 32) * lda);
        if (BKM) {
            const float* b0 = Bg + (long)kt * 32 + bc;
            float* sb = sB + stg * SBKM_ELEMS;
#pragma unroll
            for (int p = 0; p < 4; p++)
                cpa16(sb + (br + p * 32) * SA_STRIDE + bc, b0 + (long)(br + p * 32) * ldb);
        } else {
            const float* b0 = Bg + (long)kt * 32 * ldb + bc;
            float* sb = sB + stg * SBNN_ELEMS;
#pragma unroll
            for (int p = 0; p < 4; p++)
                cpa16(sb + (br + p * 8) * SBNN_STRIDE + bc, b0 + (long)(br + p * 8) * ldb);
        }
    };

    const int warp = tid >> 5, lane = tid & 31;
    const int wm = (warp & 3) * 32;
    const int wn = (warp >> 2) * 64;
    const int g = lane >> 2, t = lane & 3;

    float acc[2][8][4];
#pragma unroll
    for (int mt = 0; mt < 2; mt++)
#pragma unroll
        for (int nt = 0; nt < 8; nt++)
#pragma unroll
            for (int i = 0; i < 4; i++) acc[mt][nt][i] = 0.f;

    issue(0, 0); cp_commit();
    issue(1, 1); cp_commit();

    for (int it = 0; it < ntk; ++it) {
        int stg = it % 3;
        if (it + 2 < ntk) issue(it + 2, (it + 2) % 3);
        cp_commit();
        cp_wait2();
        __syncthreads();

        const float* sa = sA + stg * SA_ELEMS;
        const float* sb = sB + stg * (BKM ? SBKM_ELEMS : SBNN_ELEMS);
#pragma unroll
        for (int ks = 0; ks < 4; ks++) {
            const int k0 = ks * 8;
            float af[2][4];
#pragma unroll
            for (int mt = 0; mt < 2; mt++) {
                int r0 = wm + mt * 16 + g;
                af[mt][0] = sa[r0 * SA_STRIDE + k0 + t];
                af[mt][1] = sa[(r0 + 8) * SA_STRIDE + k0 + t];
                af[mt][2] = sa[r0 * SA_STRIDE + k0 + t + 4];
                af[mt][3] = sa[(r0 + 8) * SA_STRIDE + k0 + t + 4];
            }
            float bf[8][2];
#pragma unroll
            for (int nt = 0; nt < 8; nt++) {
                int c0 = wn + nt * 8 + g;
                if (BKM) {
                    bf[nt][0] = sb[c0 * SA_STRIDE + k0 + t];
                    bf[nt][1] = sb[c0 * SA_STRIDE + k0 + t + 4];
                } else {
                    bf[nt][0] = sb[(k0 + t) * SBNN_STRIDE + c0];
                    bf[nt][1] = sb[(k0 + t + 4) * SBNN_STRIDE + c0];
                }
            }
#pragma unroll
            for (int mt = 0; mt < 2; mt++)
#pragma unroll
                for (int nt = 0; nt < 8; nt++)
                    mma_tf32(acc[mt][nt], af[mt], bf[nt]);
        }
        __syncthreads();
    }

    const long co = bz * cB + hz * cH;
    const long eo = bz * eB + hz * eH;
    const int mbase = blockIdx.y * 128 + wm;
    const int nbase = blockIdx.x * 128 + wn;

#pragma unroll
    for (int mt = 0; mt < 2; mt++) {
#pragma unroll
        for (int half = 0; half < 2; half++) {
            const int row = mbase + mt * 16 + g + half * 8;
#pragma unroll
            for (int nt = 0; nt < 8; nt++) {
                const int col = nbase + nt * 8 + 2 * t;
                float v0 = acc[mt][nt][half * 2 + 0];
                float v1 = acc[mt][nt][half * 2 + 1];
                if (EPI == EPI_SCORES) {
                    if (extra[eo + col]     == 0.f) v0 += -3.4028234663852886e38f;
                    if (extra[eo + col + 1] == 0.f) v1 += -3.4028234663852886e38f;
                } else if (EPI == EPI_RND) {
                    v0 = to_tf32(v0);
                    v1 = to_tf32(v1);
                }
                *(float2*)(C + co + (long)row * ldc + col) = make_float2(v0, v1);
            }
        }
    }
}

// ---------------------------------------------------------------------------
// LayerNorm (tf32-rna rounded output)
// ---------------------------------------------------------------------------
__global__ void ln_kernel(const float* __restrict__ x, const float* __restrict__ w,
                          const float* __restrict__ b, float* __restrict__ out)
{
    __shared__ float s1[8], s2[8];
    const int row = blockIdx.x, tid = threadIdx.x;
    const int lane = tid & 31, wid = tid >> 5;
    const float4* xr = (const float4*)(x + (long)row * DD);
    float4 v0 = xr[tid], v1 = xr[tid + 256];

    float s = v0.x + v0.y + v0.z + v0.w + v1.x + v1.y + v1.z + v1.w;
    float q = v0.x*v0.x + v0.y*v0.y + v0.z*v0.z + v0.w*v0.w
            + v1.x*v1.x + v1.y*v1.y + v1.z*v1.z + v1.w*v1.w;
#pragma unroll
    for (int o = 16; o; o >>= 1) {
        s += __shfl_xor_sync(0xffffffffu, s, o);
        q += __shfl_xor_sync(0xffffffffu, q, o);
    }
    if (lane == 0) { s1[wid] = s; s2[wid] = q; }
    __syncthreads();
    if (tid < 8) {
        s = s1[tid]; q = s2[tid];
#pragma unroll
        for (int o = 4; o; o >>= 1) {
            s += __shfl_xor_sync(0xffu, s, o);
            q += __shfl_xor_sync(0xffu, q, o);
        }
        if (tid == 0) { s1[0] = s; s2[0] = q; }
    }
    __syncthreads();
    const float mu = s1[0] * (1.f / DD);
    const float var = s2[0] * (1.f / DD) - mu * mu;
    const float r = rsqrtf(var + 1e-5f);

    float4 o0, o1;
    int c0 = tid * 4, c1 = (tid + 256) * 4;
    o0.x = to_tf32((v0.x - mu) * r * w[c0+0] + b[c0+0]);
    o0.y = to_tf32((v0.y - mu) * r * w[c0+1] + b[c0+1]);
    o0.z = to_tf32((v0.z - mu) * r * w[c0+2] + b[c0+2]);
    o0.w = to_tf32((v0.w - mu) * r * w[c0+3] + b[c0+3]);
    o1.x = to_tf32((v1.x - mu) * r * w[c1+0] + b[c1+0]);
    o1.y = to_tf32((v1.y - mu) * r * w[c1+1] + b[c1+1]);
    o1.z = to_tf32((v1.z - mu) * r * w[c1+2] + b[c1+2]);
    o1.w = to_tf32((v1.w - mu) * r * w[c1+3] + b[c1+3]);
    float4* orow = (float4*)(out + (long)row * DD);
    orow[tid] = o0; orow[tid + 256] = o1;
}

// ---------------------------------------------------------------------------
// Softmax (tf32-rna rounded probs)
// ---------------------------------------------------------------------------
__global__ void softmax_kernel(float* __restrict__ sc)
{
    __shared__ float red[8];
    const long row = blockIdx.x;
    float4* p = (float4*)(sc + row * (long)SS);
    const int tid = threadIdx.x, lane = tid & 31, wid = tid >> 5;
    float4 v = p[tid];

    float m = fmaxf(fmaxf(v.x, v.y), fmaxf(v.z, v.w));
#pragma unroll
    for (int o = 16; o; o >>= 1) m = fmaxf(m, __shfl_xor_sync(0xffffffffu, m, o));
    if (lane == 0) red[wid] = m;
    __syncthreads();
    if (tid < 8) {
        m = red[tid];
#pragma unroll
        for (int o = 4; o; o >>= 1) m = fmaxf(m, __shfl_xor_sync(0xffu, m, o));
        if (tid == 0) red[0] = m;
    }
    __syncthreads();
    const float M = red[0];
    __syncthreads();

    v.x = expf(v.x - M); v.y = expf(v.y - M);
    v.z = expf(v.z - M); v.w = expf(v.w - M);
    float s = v.x + v.y + v.z + v.w;
#pragma unroll
    for (int o = 16; o; o >>= 1) s += __shfl_xor_sync(0xffffffffu, s, o);
    if (lane == 0) red[wid] = s;
    __syncthreads();
    if (tid < 8) {
        s = red[tid];
#pragma unroll
        for (int o = 4; o; o >>= 1) s += __shfl_xor_sync(0xffu, s, o);
        if (tid == 0) red[0] = s;
    }
    __syncthreads();
    const float inv = 1.f / red[0];
    v.x = to_tf32(v.x * inv); v.y = to_tf32(v.y * inv);
    v.z = to_tf32(v.z * inv); v.w = to_tf32(v.w * inv);
    p[tid] = v;
}

// ---------------------------------------------------------------------------
// Round+pack weights (2 launches so QKV gemm is our launch #4 = ncu's target)
// ---------------------------------------------------------------------------
__device__ __forceinline__ void pack4(const float* __restrict__ src, float* __restrict__ dst,
                                      int K, int NB8tot, int n8off, long s)
{
    const int kq = K >> 2;
    const int n = (int)(s / kq);
    const int k4 = (int)(s - (long)n * kq);
    float4 v = ((const float4*)src)[s];
    float vals[4];
    vals[0] = to_tf32(v.x); vals[1] = to_tf32(v.y);
    vals[2] = to_tf32(v.z); vals[3] = to_tf32(v.w);
    const int gg = n & 7;
    const long n8 = (n >> 3) + n8off;
    const int swz = (gg & 3) << 1;
#pragma unroll
    for (int c = 0; c < 4; c++) {
        const int k = k4 * 4 + c;
        const int kt = k >> 5, ks = (k >> 3) & 3, h = (k >> 2) & 1, t = k & 3;
        const long base = (((long)kt * NB8tot + n8) * 32 + (gg * 4 + t)) * 8;
        dst[base + ((ks * 2 + h) ^ swz)] = vals[c];
    }
}

__global__ void pack_attn(
    const float* __restrict__ Wq, const float* __restrict__ Wk,
    const float* __restrict__ Wv, const float* __restrict__ Wo,
    float* __restrict__ dqkv, float* __restrict__ dwo)
{
    const long M1 = 1048576;
    const long i = (long)blockIdx.x * 256 + threadIdx.x;
    if      (i < 1*M1) pack4(Wq, dqkv, DD, 768, 0,   i);
    else if (i < 2*M1) pack4(Wk, dqkv, DD, 768, 256, i - 1*M1);
    else if (i < 3*M1) pack4(Wv, dqkv, DD, 768, 512, i - 2*M1);
    else               pack4(Wo, dwo,  DD, 256, 0,   i - 3*M1);
}

__global__ void pack_mlp(
    const float* __restrict__ W1, const float* __restrict__ W2,
    float* __restrict__ dw1, float* __restrict__ dw2)
{
    const long M4 = 4194304;
    const long i = (long)blockIdx.x * 256 + threadIdx.x;
    if (i < M4) pack4(W1, dw1, DD, 1024, 0, i);
    else        pack4(W2, dw2, II, 256, 0,  i - M4);
}

// ---------------------------------------------------------------------------
// Host launch
// ---------------------------------------------------------------------------
static const int SMEM_KM = 3 * (SA_ELEMS + SBKM_ELEMS) * 4;
static const int SMEM_NN = 3 * (SA_ELEMS + SBNN_ELEMS) * 4;

extern "C" void kernel_launch(void* const* d_in, const int* in_sizes, int n_in,
                              void* d_out, int out_size)
{
    const float* hid   = (const float*)d_in[1];
    const float* amask = (const float*)d_in[2];
    const float* Wq = (const float*)d_in[4];  const float* bq = (const float*)d_in[5];
    const float* Wk = (const float*)d_in[6];  const float* bk = (const float*)d_in[7];
    const float* Wv = (const float*)d_in[8];  const float* bv = (const float*)d_in[9];
    const float* Wo = (const float*)d_in[10]; const float* bo = (const float*)d_in[11];
    const float* l1w = (const float*)d_in[12]; const float* l1b = (const float*)d_in[13];
    const float* l2w = (const float*)d_in[14]; const float* l2b = (const float*)d_in[15];
    const float* W1 = (const float*)d_in[16]; const float* b1 = (const float*)d_in[17];
    const float* W2 = (const float*)d_in[18]; const float* b2 = (const float*)d_in[19];
    float* out = (float*)d_out;

    void* p;
    cudaGetSymbolAddress(&p, g_xln1);  float* xln1 = (float*)p;
    cudaGetSymbolAddress(&p, g_q);     float* q    = (float*)p;
    cudaGetSymbolAddress(&p, g_k);     float* k    = (float*)p;
    cudaGetSymbolAddress(&p, g_v);     float* v    = (float*)p;
    cudaGetSymbolAddress(&p, g_scores);float* sc   = (float*)p;
    cudaGetSymbolAddress(&p, g_attn);  float* attn = (float*)p;
    cudaGetSymbolAddress(&p, g_hidden);float* hd2  = (float*)p;
    cudaGetSymbolAddress(&p, g_yln2);  float* yln2 = (float*)p;
    cudaGetSymbolAddress(&p, g_mid);   float* mid  = (float*)p;
    cudaGetSymbolAddress(&p, g_wqkv);  float* wqkv = (float*)p;
    cudaGetSymbolAddress(&p, g_wo);    float* wo   = (float*)p;
    cudaGetSymbolAddress(&p, g_w1);    float* w1   = (float*)p;
    cudaGetSymbolAddress(&p, g_w2);    float* w2   = (float*)p;

    cudaFuncSetAttribute((const void*)gemm_big<EPI_QKV3>,   cudaFuncAttributeMaxDynamicSharedMemorySize, GB_SMEM);
    cudaFuncSetAttribute((const void*)gemm_big<EPI_BIASRES>,cudaFuncAttributeMaxDynamicSharedMemorySize, GB_SMEM);
    cudaFuncSetAttribute((const void*)gemm_big<EPI_GELU>,   cudaFuncAttributeMaxDynamicSharedMemorySize, GB_SMEM);
    cudaFuncSetAttribute((const void*)gemm_k<true,  EPI_SCORES>, cudaFuncAttributeMaxDynamicSharedMemorySize, SMEM_KM);
    cudaFuncSetAttribute((const void*)gemm_k<false, EPI_RND>,    cudaFuncAttributeMaxDynamicSharedMemorySize, SMEM_NN);

    const float qscale = 0.08838834764831845f;  // 128^-0.5

    // 1) pack attn weights (4M float4)
    pack_attn<<<16384, 256>>>(Wq, Wk, Wv, Wo, wqkv, wo);
    // 2) pack mlp weights (8M float4)
    pack_mlp<<<32768, 256>>>(W1, W2, w1, w2);
    // 3) LN1
    ln_kernel<<<MTOK, 256>>>(hid, l1w, l1b, xln1);
    // 4) fused QKV projection [4096 x 6144]  <-- ncu profiles this launch
    gemm_big<EPI_QKV3><<<dim3(24, 32), 512, GB_SMEM>>>(
        xln1, wqkv, q, k, v, DD, 768, DD, bq, bk, bv, nullptr, qscale);

    // 5) scores = q @ k^T (+mask)
    gemm_k<true, EPI_SCORES><<<dim3(8, 8, BB*HH), 256, SMEM_KM>>>(
        q, k, sc, DD, DD, SS, 4,
        (long)SS*DD, HDIM, (long)SS*DD, HDIM,
        (long)HH*SS*SS, (long)SS*SS, (long)SS, 0, HH,
        nullptr, amask, 1.0f);

    // 6) softmax
    softmax_kernel<<<BB*HH*SS, 256>>>(sc);

    // 7) attn = P @ V
    gemm_k<false, EPI_RND><<<dim3(1, 8, BB*HH), 256, SMEM_NN>>>(
        sc, v, attn, SS, DD, DD, 32,
        (long)HH*SS*SS, (long)SS*SS, (long)SS*DD, HDIM,
        (long)SS*DD, HDIM, 0, 0, HH,
        nullptr, nullptr, 1.0f);

    // 8) hidden = residual + attn @ Wo^T + bo
    gemm_big<EPI_BIASRES><<<dim3(8, 32), 512, GB_SMEM>>>(
        attn, wo, hd2, nullptr, nullptr, DD, 256, DD, bo, nullptr, nullptr, hid, 1.0f);

    // 9) LN2
    ln_kernel<<<MTOK, 256>>>(hd2, l2w, l2b, yln2);

    // 10) mid = gelu(yln2 @ W1^T + b1)
    gemm_big<EPI_GELU><<<dim3(32, 32), 512, GB_SMEM>>>(
        yln2, w1, mid, nullptr, nullptr, DD, 1024, II, b1, nullptr, nullptr, nullptr, 1.0f);

    // 11) out = hidden + mid @ W2^T + b2 (K=8192)
    gemm_big<EPI_BIASRES><<<dim3(8, 32), 512, GB_SMEM>>>(
        mid, w2, out, nullptr, nullptr, II, 256, DD, b2, nullptr, nullptr, hd2, 1.0f);
}

// round 10
// speedup vs baseline: 1.1272x; 1.1071x over previous
#include <cuda_runtime.h>
#include <cstdint>
#include <cmath>

// ---------------------------------------------------------------------------
// Problem constants
// ---------------------------------------------------------------------------
#define BB 4
#define SS 1024
#define DD 2048
#define HH 16
#define HDIM 128
#define II 8192
#define MTOK (BB*SS)

// ---------------------------------------------------------------------------
// Scratch
// ---------------------------------------------------------------------------
__device__ __align__(256) float g_xln1 [MTOK*DD];
__device__ __align__(256) float g_q    [MTOK*DD];
__device__ __align__(256) float g_k    [MTOK*DD];
__device__ __align__(256) float g_v    [MTOK*DD];
__device__ __align__(256) float g_attn [MTOK*DD];
__device__ __align__(256) float g_hidden[MTOK*DD];
__device__ __align__(256) float g_yln2 [MTOK*DD];
__device__ __align__(256) float g_mid  [MTOK*II];
__device__ __align__(256) float g_wqkv[3*DD*DD];   // packed fragments, NB8=768
__device__ __align__(256) float g_wo[DD*DD];       // packed, NB8=256
__device__ __align__(256) float g_w1[II*DD];       // packed, NB8=1024
__device__ __align__(256) float g_w2[DD*II];       // packed, NB8=256

// ---------------------------------------------------------------------------
// Helpers
// ---------------------------------------------------------------------------
__device__ __forceinline__ float to_tf32(float x) {
    float r;
    asm("cvt.rna.tf32.f32 %0, %1;" : "=f"(r) : "f"(x));
    return r;
}
__device__ __forceinline__ void cpa16(void* sdst, const void* gsrc) {
    uint32_t s = (uint32_t)__cvta_generic_to_shared(sdst);
    asm volatile("cp.async.cg.shared.global [%0], [%1], 16;" :: "r"(s), "l"(gsrc));
}
__device__ __forceinline__ void cp_commit() { asm volatile("cp.async.commit_group;"); }
__device__ __forceinline__ void cp_wait1()  { asm volatile("cp.async.wait_group 1;"); }
__device__ __forceinline__ void cp_wait2()  { asm volatile("cp.async.wait_group 2;"); }

__device__ __forceinline__ void mma_tf32(float c[4], const float a[4], const float b[2]) {
    const uint32_t* A = reinterpret_cast<const uint32_t*>(a);
    const uint32_t* Bp = reinterpret_cast<const uint32_t*>(b);
    asm volatile(
        "mma.sync.aligned.m16n8k8.row.col.f32.tf32.tf32.f32 "
        "{%0,%1,%2,%3}, {%4,%5,%6,%7}, {%8,%9}, {%0,%1,%2,%3};"
        : "+f"(c[0]), "+f"(c[1]), "+f"(c[2]), "+f"(c[3])
        : "r"(A[0]), "r"(A[1]), "r"(A[2]), "r"(A[3]), "r"(Bp[0]), "r"(Bp[1]));
}

enum { EPI_QKV3 = 0, EPI_BIASRES = 3, EPI_GELU = 4 };

// ===========================================================================
// gemm_big (R6-exact, best measured): CTA 128x256x32, 256 thr, 8 warps 2Mx4N,
// warp tile 64x64, 3-stage cp.async, packed-B w/ baked bank swizzle,
// register double-buffered fragments.
// ===========================================================================
#define GB_AS 36
#define GB_A_FLOATS (128*GB_AS)
#define GB_B_FLOATS 8192
#define GB_SMEM (3*(GB_A_FLOATS+GB_B_FLOATS)*4)   // 153600 bytes

template<int EPI>
__global__ void __launch_bounds__(256, 1) gemm_big(
    const float* __restrict__ A, const float* __restrict__ Bp,
    float* __restrict__ C0, float* __restrict__ C1, float* __restrict__ C2,
    int K, int NB8tot, int ldc,
    const float* __restrict__ bias0, const float* __restrict__ bias1,
    const float* __restrict__ bias2, const float* __restrict__ extra, float scale)
{
    extern __shared__ float sm[];
    float* sA = sm;
    float* sB = sm + 3 * GB_A_FLOATS;

    const int tid = threadIdx.x;
    const int ntk = K >> 5;

    const float* Ab = A + (long)blockIdx.y * 128 * K;
    const long bslice = (long)blockIdx.x * 8192;

    auto issue = [&](int kt, int stg) {
        float* sa = sA + stg * GB_A_FLOATS;
        const float* ag = Ab + (long)kt * 32;
#pragma unroll
        for (int i = 0; i < 4; i++) {
            int c = tid + i * 256;
            int r = c >> 3, cc = (c & 7) * 4;
            cpa16(sa + r * GB_AS + cc, ag + (long)r * K + cc);
        }
        float* sb = sB + stg * GB_B_FLOATS;
        const float* bg = Bp + (long)kt * NB8tot * 256 + bslice;
#pragma unroll
        for (int i = 0; i < 8; i++) {
            int c = tid + i * 256;
            cpa16(sb + c * 4, bg + (long)c * 4);
        }
    };

    const int warp = tid >> 5, lane = tid & 31;
    const int wm = (warp & 1) * 64;
    const int wnidx = warp >> 1;
    const int g = lane >> 2, t = lane & 3;
    const int bswz = (g & 3) << 1;

    float acc[4][8][4];
#pragma unroll
    for (int mt = 0; mt < 4; mt++)
#pragma unroll
        for (int nt = 0; nt < 8; nt++)
#pragma unroll
            for (int i = 0; i < 4; i++) acc[mt][nt][i] = 0.f;

    issue(0, 0); cp_commit();
    issue(1, 1); cp_commit();

    for (int it = 0; it < ntk; ++it) {
        const int stg = it % 3;
        if (it + 2 < ntk) issue(it + 2, (it + 2) % 3);
        cp_commit();
        cp_wait2();
        __syncthreads();

        const float* sa  = sA + stg * GB_A_FLOATS;
        const float* sbw = sB + stg * GB_B_FLOATS + wnidx * 2048 + lane * 8;

        float af[2][4][4];
        float bf[2][8][2];

#pragma unroll
        for (int mt = 0; mt < 4; mt++) {
            const int r0 = wm + mt * 16 + g;
            af[0][mt][0] = sa[r0 * GB_AS + t];
            af[0][mt][1] = sa[(r0 + 8) * GB_AS + t];
            af[0][mt][2] = sa[r0 * GB_AS + t + 4];
            af[0][mt][3] = sa[(r0 + 8) * GB_AS + t + 4];
        }
#pragma unroll
        for (int nt = 0; nt < 8; nt++) {
            float2 b = *(const float2*)(sbw + nt * 256 + bswz);
            bf[0][nt][0] = b.x; bf[0][nt][1] = b.y;
        }

#pragma unroll
        for (int ks = 0; ks < 4; ks++) {
            const int cur = ks & 1, nxt = cur ^ 1;
            if (ks < 3) {
                const int k0 = (ks + 1) * 8;
#pragma unroll
                for (int mt = 0; mt < 4; mt++) {
                    const int r0 = wm + mt * 16 + g;
                    af[nxt][mt][0] = sa[r0 * GB_AS + k0 + t];
                    af[nxt][mt][1] = sa[(r0 + 8) * GB_AS + k0 + t];
                    af[nxt][mt][2] = sa[r0 * GB_AS + k0 + t + 4];
                    af[nxt][mt][3] = sa[(r0 + 8) * GB_AS + k0 + t + 4];
                }
                const int bo = ((ks + 1) * 2) ^ bswz;
#pragma unroll
                for (int nt = 0; nt < 8; nt++) {
                    float2 b = *(const float2*)(sbw + nt * 256 + bo);
                    bf[nxt][nt][0] = b.x; bf[nxt][nt][1] = b.y;
                }
            }
#pragma unroll
            for (int mt = 0; mt < 4; mt++)
#pragma unroll
                for (int nt = 0; nt < 8; nt++)
                    mma_tf32(acc[mt][nt], af[cur][mt], bf[cur][nt]);
        }
        __syncthreads();
    }

    const int wn = wnidx * 64;
    const int nbase = blockIdx.x * 256;
    const int mbase = blockIdx.y * 128 + wm;

    float* dst = C0;
    const float* bs = bias0;
    float sc = scale;
    int nloc = nbase;
    if (EPI == EPI_QKV3) {
        const int seg = nbase >> 11;
        nloc = nbase & 2047;
        if (seg == 1) { dst = C1; bs = bias1; sc = 1.0f; }
        else if (seg == 2) { dst = C2; bs = bias2; sc = 1.0f; }
    }

#pragma unroll
    for (int mt = 0; mt < 4; mt++) {
#pragma unroll
        for (int half = 0; half < 2; half++) {
            const int row = mbase + mt * 16 + g + half * 8;
            const long crow = (long)row * ldc;
#pragma unroll
            for (int nt = 0; nt < 8; nt++) {
                const int cc = wn + nt * 8 + 2 * t;
                const int col = nloc + cc;
                float v0 = acc[mt][nt][half * 2 + 0];
                float v1 = acc[mt][nt][half * 2 + 1];
                if (EPI == EPI_QKV3) {
                    v0 = to_tf32((v0 + bs[col]) * sc);
                    v1 = to_tf32((v1 + bs[col + 1]) * sc);
                } else if (EPI == EPI_BIASRES) {
                    v0 += bs[col]     + extra[crow + col];
                    v1 += bs[col + 1] + extra[crow + col + 1];
                } else if (EPI == EPI_GELU) {
                    v0 += bs[col];
                    v1 += bs[col + 1];
                    v0 = to_tf32(0.5f * v0 * (1.f + erff(v0 * 0.7071067811865476f)));
                    v1 = to_tf32(0.5f * v1 * (1.f + erff(v1 * 0.7071067811865476f)));
                }
                *(float2*)(dst + crow + col) = make_float2(v0, v1);
            }
        }
    }
}

// ===========================================================================
// Flash attention: grid (8 qblocks, 64 bh), 256 thr / 8 warps, each warp owns
// 16 full q-rows. KB=64 kv-block, K double-buffered, online softmax with
// warp-local (t-lane shuffle) row stats, P via per-warp-private smem.
// ===========================================================================
#define FA_KB 64
#define FA_QSTR 132
#define FA_KSTR 132
#define FA_VSTR 136
#define FA_PSTR 68
#define FA_SQ 0
#define FA_SK 16896
#define FA_SV 33792
#define FA_SP 42496
#define FA_SM 51200
#define FA_TOTALF 52224
#define FA_SMEM (FA_TOTALF*4)     // 208896 bytes

__global__ void __launch_bounds__(256, 1) flash_kernel(
    const float* __restrict__ Qg, const float* __restrict__ Kg,
    const float* __restrict__ Vg, const float* __restrict__ amask,
    float* __restrict__ Og)
{
    extern __shared__ float sm[];
    const int tid = threadIdx.x;
    const int qb = blockIdx.x, bh = blockIdx.y;
    const int b = bh >> 4, h = bh & 15;
    const long qrow0 = (long)b * SS + qb * 128;

    // mask -> additive values
    for (int i = tid; i < SS; i += 256)
        sm[FA_SM + i] = (amask[b * SS + i] == 0.f) ? -3.4028234663852886e38f : 0.f;

    // stage Q tile 128x128
    {
        const float* qg = Qg + qrow0 * DD + h * HDIM;
#pragma unroll
        for (int i = 0; i < 16; i++) {
            int c = tid + i * 256;
            int r = c >> 5, ch = c & 31;
            cpa16(sm + FA_SQ + r * FA_QSTR + ch * 4, qg + (long)r * DD + ch * 4);
        }
        cp_commit();
    }

    auto loadK = [&](int kb, int buf) {
        const float* kg = Kg + ((long)b * SS + kb * FA_KB) * DD + h * HDIM;
        float* dst = sm + FA_SK + buf * 8448;
#pragma unroll
        for (int i = 0; i < 8; i++) {
            int c = tid + i * 256;
            int r = c >> 5, ch = c & 31;
            cpa16(dst + r * FA_KSTR + ch * 4, kg + (long)r * DD + ch * 4);
        }
    };
    auto loadV = [&](int kb) {
        const float* vg = Vg + ((long)b * SS + kb * FA_KB) * DD + h * HDIM;
        float* dst = sm + FA_SV;
#pragma unroll
        for (int i = 0; i < 8; i++) {
            int c = tid + i * 256;
            int r = c >> 5, ch = c & 31;
            cpa16(dst + r * FA_VSTR + ch * 4, vg + (long)r * DD + ch * 4);
        }
    };
    loadK(0, 0); cp_commit();   // groups: Q, K0
    loadV(0);    cp_commit();   // V0

    const int w = tid >> 5, lane = tid & 31;
    const int g = lane >> 2, t = lane & 3;

    float m0 = -3.4028234663852886e38f, m1 = -3.4028234663852886e38f;
    float l0 = 0.f, l1 = 0.f;
    float o[16][4];
#pragma unroll
    for (int nt = 0; nt < 16; nt++)
#pragma unroll
        for (int i = 0; i < 4; i++) o[nt][i] = 0.f;

    const float* sq = sm + FA_SQ + (w * 16 + g) * FA_QSTR;
    float* sp = sm + FA_SP + (w * 16 + g) * FA_PSTR;

    for (int kb = 0; kb < SS / FA_KB; kb++) {
        const int buf = kb & 1;
        cp_wait1();                 // K(kb) loaded (V(kb) still pending)
        __syncthreads();
        if (kb + 1 < SS / FA_KB) loadK(kb + 1, buf ^ 1);
        cp_commit();

        // ---- S = Q K^T (warp: 16 rows x 64 cols) ----
        const float* sk = sm + FA_SK + buf * 8448;
        float s[8][4];
#pragma unroll
        for (int nt = 0; nt < 8; nt++)
#pragma unroll
            for (int i = 0; i < 4; i++) s[nt][i] = 0.f;
#pragma unroll
        for (int ks = 0; ks < 16; ks++) {
            float af[4];
            af[0] = sq[ks * 8 + t];
            af[1] = sq[8 * FA_QSTR + ks * 8 + t];
            af[2] = sq[ks * 8 + t + 4];
            af[3] = sq[8 * FA_QSTR + ks * 8 + t + 4];
#pragma unroll
            for (int nt = 0; nt < 8; nt++) {
                float bf[2];
                bf[0] = sk[(nt * 8 + g) * FA_KSTR + ks * 8 + t];
                bf[1] = sk[(nt * 8 + g) * FA_KSTR + ks * 8 + t + 4];
                mma_tf32(s[nt], af, bf);
            }
        }

        // ---- mask + online softmax ----
        float mn0 = m0, mn1 = m1;
#pragma unroll
        for (int nt = 0; nt < 8; nt++) {
            float ma = sm[FA_SM + kb * FA_KB + nt * 8 + 2 * t];
            float mb = sm[FA_SM + kb * FA_KB + nt * 8 + 2 * t + 1];
            s[nt][0] += ma; s[nt][1] += mb; s[nt][2] += ma; s[nt][3] += mb;
            mn0 = fmaxf(mn0, fmaxf(s[nt][0], s[nt][1]));
            mn1 = fmaxf(mn1, fmaxf(s[nt][2], s[nt][3]));
        }
        mn0 = fmaxf(mn0, __shfl_xor_sync(0xffffffffu, mn0, 1));
        mn0 = fmaxf(mn0, __shfl_xor_sync(0xffffffffu, mn0, 2));
        mn1 = fmaxf(mn1, __shfl_xor_sync(0xffffffffu, mn1, 1));
        mn1 = fmaxf(mn1, __shfl_xor_sync(0xffffffffu, mn1, 2));
        const float sc0 = __expf(m0 - mn0), sc1 = __expf(m1 - mn1);
        m0 = mn0; m1 = mn1;

        float ls0 = 0.f, ls1 = 0.f;
#pragma unroll
        for (int nt = 0; nt < 8; nt++) {
            float p0 = __expf(s[nt][0] - m0), p1 = __expf(s[nt][1] - m0);
            float p2 = __expf(s[nt][2] - m1), p3 = __expf(s[nt][3] - m1);
            ls0 += p0 + p1; ls1 += p2 + p3;
            *(float2*)(sp + nt * 8 + 2 * t) = make_float2(to_tf32(p0), to_tf32(p1));
            *(float2*)(sp + 8 * FA_PSTR + nt * 8 + 2 * t) = make_float2(to_tf32(p2), to_tf32(p3));
        }
        ls0 += __shfl_xor_sync(0xffffffffu, ls0, 1);
        ls0 += __shfl_xor_sync(0xffffffffu, ls0, 2);
        ls1 += __shfl_xor_sync(0xffffffffu, ls1, 1);
        ls1 += __shfl_xor_sync(0xffffffffu, ls1, 2);
        l0 = l0 * sc0 + ls0;
        l1 = l1 * sc1 + ls1;
#pragma unroll
        for (int nt = 0; nt < 16; nt++) {
            o[nt][0] *= sc0; o[nt][1] *= sc0;
            o[nt][2] *= sc1; o[nt][3] *= sc1;
        }

        cp_wait1();                 // V(kb) loaded (K(kb+1) pending)
        __syncthreads();            // sV visible + sP writes (own-warp) ordered

        // ---- O += P V ----
        const float* sv = sm + FA_SV;
#pragma unroll
        for (int ks = 0; ks < 8; ks++) {
            float af[4];
            af[0] = sp[ks * 8 + t];
            af[1] = sp[8 * FA_PSTR + ks * 8 + t];
            af[2] = sp[ks * 8 + t + 4];
            af[3] = sp[8 * FA_PSTR + ks * 8 + t + 4];
#pragma unroll
            for (int nt = 0; nt < 16; nt++) {
                float bf[2];
                bf[0] = sv[(ks * 8 + t) * FA_VSTR + nt * 8 + g];
                bf[1] = sv[(ks * 8 + t + 4) * FA_VSTR + nt * 8 + g];
                mma_tf32(o[nt], af, bf);
            }
        }
        __syncthreads();            // all warps done reading sV
        if (kb + 1 < SS / FA_KB) loadV(kb + 1);
        cp_commit();
    }

    // ---- epilogue: normalize + store (rounded for Wo GEMM) ----
    const float inv0 = 1.f / l0, inv1 = 1.f / l1;
    float* og = Og + (qrow0 + w * 16 + g) * DD + h * HDIM;
#pragma unroll
    for (int nt = 0; nt < 16; nt++) {
        *(float2*)(og + nt * 8 + 2 * t) =
            make_float2(to_tf32(o[nt][0] * inv0), to_tf32(o[nt][1] * inv0));
        *(float2*)(og + 8 * DD + nt * 8 + 2 * t) =
            make_float2(to_tf32(o[nt][2] * inv1), to_tf32(o[nt][3] * inv1));
    }
}

// ---------------------------------------------------------------------------
// LayerNorm (tf32-rna rounded output)
// ---------------------------------------------------------------------------
__global__ void ln_kernel(const float* __restrict__ x, const float* __restrict__ w,
                          const float* __restrict__ b, float* __restrict__ out)
{
    __shared__ float s1[8], s2[8];
    const int row = blockIdx.x, tid = threadIdx.x;
    const int lane = tid & 31, wid = tid >> 5;
    const float4* xr = (const float4*)(x + (long)row * DD);
    float4 v0 = xr[tid], v1 = xr[tid + 256];

    float s = v0.x + v0.y + v0.z + v0.w + v1.x + v1.y + v1.z + v1.w;
    float q = v0.x*v0.x + v0.y*v0.y + v0.z*v0.z + v0.w*v0.w
            + v1.x*v1.x + v1.y*v1.y + v1.z*v1.z + v1.w*v1.w;
#pragma unroll
    for (int o = 16; o; o >>= 1) {
        s += __shfl_xor_sync(0xffffffffu, s, o);
        q += __shfl_xor_sync(0xffffffffu, q, o);
    }
    if (lane == 0) { s1[wid] = s; s2[wid] = q; }
    __syncthreads();
    if (tid < 8) {
        s = s1[tid]; q = s2[tid];
#pragma unroll
        for (int o = 4; o; o >>= 1) {
            s += __shfl_xor_sync(0xffu, s, o);
            q += __shfl_xor_sync(0xffu, q, o);
        }
        if (tid == 0) { s1[0] = s; s2[0] = q; }
    }
    __syncthreads();
    const float mu = s1[0] * (1.f / DD);
    const float var = s2[0] * (1.f / DD) - mu * mu;
    const float r = rsqrtf(var + 1e-5f);

    float4 o0, o1;
    int c0 = tid * 4, c1 = (tid + 256) * 4;
    o0.x = to_tf32((v0.x - mu) * r * w[c0+0] + b[c0+0]);
    o0.y = to_tf32((v0.y - mu) * r * w[c0+1] + b[c0+1]);
    o0.z = to_tf32((v0.z - mu) * r * w[c0+2] + b[c0+2]);
    o0.w = to_tf32((v0.w - mu) * r * w[c0+3] + b[c0+3]);
    o1.x = to_tf32((v1.x - mu) * r * w[c1+0] + b[c1+0]);
    o1.y = to_tf32((v1.y - mu) * r * w[c1+1] + b[c1+1]);
    o1.z = to_tf32((v1.z - mu) * r * w[c1+2] + b[c1+2]);
    o1.w = to_tf32((v1.w - mu) * r * w[c1+3] + b[c1+3]);
    float4* orow = (float4*)(out + (long)row * DD);
    orow[tid] = o0; orow[tid + 256] = o1;
}

// ---------------------------------------------------------------------------
// Round+pack weights
// ---------------------------------------------------------------------------
__device__ __forceinline__ void pack4(const float* __restrict__ src, float* __restrict__ dst,
                                      int K, int NB8tot, int n8off, long s)
{
    const int kq = K >> 2;
    const int n = (int)(s / kq);
    const int k4 = (int)(s - (long)n * kq);
    float4 v = ((const float4*)src)[s];
    float vals[4];
    vals[0] = to_tf32(v.x); vals[1] = to_tf32(v.y);
    vals[2] = to_tf32(v.z); vals[3] = to_tf32(v.w);
    const int gg = n & 7;
    const long n8 = (n >> 3) + n8off;
    const int swz = (gg & 3) << 1;
#pragma unroll
    for (int c = 0; c < 4; c++) {
        const int k = k4 * 4 + c;
        const int kt = k >> 5, ks = (k >> 3) & 3, h = (k >> 2) & 1, t = k & 3;
        const long base = (((long)kt * NB8tot + n8) * 32 + (gg * 4 + t)) * 8;
        dst[base + ((ks * 2 + h) ^ swz)] = vals[c];
    }
}

__global__ void pack_attn(
    const float* __restrict__ Wq, const float* __restrict__ Wk,
    const float* __restrict__ Wv, const float* __restrict__ Wo,
    float* __restrict__ dqkv, float* __restrict__ dwo)
{
    const long M1 = 1048576;
    const long i = (long)blockIdx.x * 256 + threadIdx.x;
    if      (i < 1*M1) pack4(Wq, dqkv, DD, 768, 0,   i);
    else if (i < 2*M1) pack4(Wk, dqkv, DD, 768, 256, i - 1*M1);
    else if (i < 3*M1) pack4(Wv, dqkv, DD, 768, 512, i - 2*M1);
    else               pack4(Wo, dwo,  DD, 256, 0,   i - 3*M1);
}

__global__ void pack_mlp(
    const float* __restrict__ W1, const float* __restrict__ W2,
    float* __restrict__ dw1, float* __restrict__ dw2)
{
    const long M4 = 4194304;
    const long i = (long)blockIdx.x * 256 + threadIdx.x;
    if (i < M4) pack4(W1, dw1, DD, 1024, 0, i);
    else        pack4(W2, dw2, II, 256, 0,  i - M4);
}

// ---------------------------------------------------------------------------
// Host launch
// ---------------------------------------------------------------------------
extern "C" void kernel_launch(void* const* d_in, const int* in_sizes, int n_in,
                              void* d_out, int out_size)
{
    const float* hid   = (const float*)d_in[1];
    const float* amask = (const float*)d_in[2];
    const float* Wq = (const float*)d_in[4];  const float* bq = (const float*)d_in[5];
    const float* Wk = (const float*)d_in[6];  const float* bk = (const float*)d_in[7];
    const float* Wv = (const float*)d_in[8];  const float* bv = (const float*)d_in[9];
    const float* Wo = (const float*)d_in[10]; const float* bo = (const float*)d_in[11];
    const float* l1w = (const float*)d_in[12]; const float* l1b = (const float*)d_in[13];
    const float* l2w = (const float*)d_in[14]; const float* l2b = (const float*)d_in[15];
    const float* W1 = (const float*)d_in[16]; const float* b1 = (const float*)d_in[17];
    const float* W2 = (const float*)d_in[18]; const float* b2 = (const float*)d_in[19];
    float* out = (float*)d_out;

    void* p;
    cudaGetSymbolAddress(&p, g_xln1);  float* xln1 = (float*)p;
    cudaGetSymbolAddress(&p, g_q);     float* q    = (float*)p;
    cudaGetSymbolAddress(&p, g_k);     float* k    = (float*)p;
    cudaGetSymbolAddress(&p, g_v);     float* v    = (float*)p;
    cudaGetSymbolAddress(&p, g_attn);  float* attn = (float*)p;
    cudaGetSymbolAddress(&p, g_hidden);float* hd2  = (float*)p;
    cudaGetSymbolAddress(&p, g_yln2);  float* yln2 = (float*)p;
    cudaGetSymbolAddress(&p, g_mid);   float* mid  = (float*)p;
    cudaGetSymbolAddress(&p, g_wqkv);  float* wqkv = (float*)p;
    cudaGetSymbolAddress(&p, g_wo);    float* wo   = (float*)p;
    cudaGetSymbolAddress(&p, g_w1);    float* w1   = (float*)p;
    cudaGetSymbolAddress(&p, g_w2);    float* w2   = (float*)p;

    cudaFuncSetAttribute((const void*)gemm_big<EPI_QKV3>,   cudaFuncAttributeMaxDynamicSharedMemorySize, GB_SMEM);
    cudaFuncSetAttribute((const void*)gemm_big<EPI_BIASRES>,cudaFuncAttributeMaxDynamicSharedMemorySize, GB_SMEM);
    cudaFuncSetAttribute((const void*)gemm_big<EPI_GELU>,   cudaFuncAttributeMaxDynamicSharedMemorySize, GB_SMEM);
    cudaFuncSetAttribute((const void*)flash_kernel,         cudaFuncAttributeMaxDynamicSharedMemorySize, FA_SMEM);

    const float qscale = 0.08838834764831845f;  // 128^-0.5

    // 1) pack attn weights
    pack_attn<<<16384, 256>>>(Wq, Wk, Wv, Wo, wqkv, wo);
    // 2) LN1
    ln_kernel<<<MTOK, 256>>>(hid, l1w, l1b, xln1);
    // 3) fused QKV projection [4096 x 6144]
    gemm_big<EPI_QKV3><<<dim3(24, 32), 256, GB_SMEM>>>(
        xln1, wqkv, q, k, v, DD, 768, DD, bq, bk, bv, nullptr, qscale);
    // 4) flash attention  <-- ncu profiles this launch
    flash_kernel<<<dim3(8, BB*HH), 256, FA_SMEM>>>(q, k, v, amask, attn);
    // 5) hidden = residual + attn @ Wo^T + bo
    gemm_big<EPI_BIASRES><<<dim3(8, 32), 256, GB_SMEM>>>(
        attn, wo, hd2, nullptr, nullptr, DD, 256, DD, bo, nullptr, nullptr, hid, 1.0f);
    // 6) LN2
    ln_kernel<<<MTOK, 256>>>(hd2, l2w, l2b, yln2);
    // 7) pack mlp weights
    pack_mlp<<<32768, 256>>>(W1, W2, w1, w2);
    // 8) mid = gelu(yln2 @ W1^T + b1)
    gemm_big<EPI_GELU><<<dim3(32, 32), 256, GB_SMEM>>>(
        yln2, w1, mid, nullptr, nullptr, DD, 1024, II, b1, nullptr, nullptr, nullptr, 1.0f);
    // 9) out = hidden + mid @ W2^T + b2 (K=8192)
    gemm_big<EPI_BIASRES><<<dim3(8, 32), 256, GB_SMEM>>>(
        mid, w2, out, nullptr, nullptr, II, 256, DD, b2, nullptr, nullptr, hd2, 1.0f);
}

// round 11
// speedup vs baseline: 1.6514x; 1.4651x over previous
#include <cuda_runtime.h>
#include <cuda_fp16.h>
#include <cstdint>
#include <cmath>

// ---------------------------------------------------------------------------
// Problem constants
// ---------------------------------------------------------------------------
#define BB 4
#define SS 1024
#define DD 2048
#define HH 16
#define HDIM 128
#define II 8192
#define MTOK (BB*SS)

// ---------------------------------------------------------------------------
// Scratch
// ---------------------------------------------------------------------------
__device__ __align__(256) __half g_xln1h[MTOK*DD];
__device__ __align__(256) float  g_q    [MTOK*DD];
__device__ __align__(256) float  g_k    [MTOK*DD];
__device__ __align__(256) float  g_v    [MTOK*DD];
__device__ __align__(256) __half g_attnh[MTOK*DD];
__device__ __align__(256) float  g_hidden[MTOK*DD];
__device__ __align__(256) __half g_yln2h[MTOK*DD];
__device__ __align__(256) __half g_midh [MTOK*II];
__device__ __align__(256) __half g_wqkv[3*DD*DD];   // fp16 fragment-packed, NB8=768
__device__ __align__(256) __half g_wo[DD*DD];       // NB8=256
__device__ __align__(256) __half g_w1[II*DD];       // NB8=1024
__device__ __align__(256) __half g_w2[DD*II];       // NB8=256

// ---------------------------------------------------------------------------
// Helpers
// ---------------------------------------------------------------------------
__device__ __forceinline__ float to_tf32(float x) {
    float r;
    asm("cvt.rna.tf32.f32 %0, %1;" : "=f"(r) : "f"(x));
    return r;
}
__device__ __forceinline__ void cpa16(void* sdst, const void* gsrc) {
    uint32_t s = (uint32_t)__cvta_generic_to_shared(sdst);
    asm volatile("cp.async.cg.shared.global [%0], [%1], 16;" :: "r"(s), "l"(gsrc));
}
__device__ __forceinline__ void cp_commit() { asm volatile("cp.async.commit_group;"); }
__device__ __forceinline__ void cp_wait1()  { asm volatile("cp.async.wait_group 1;"); }
__device__ __forceinline__ void cp_wait2()  { asm volatile("cp.async.wait_group 2;"); }

// tf32 mma (flash kernel)
__device__ __forceinline__ void mma_tf32(float c[4], const float a[4], const float b[2]) {
    const uint32_t* A = reinterpret_cast<const uint32_t*>(a);
    const uint32_t* Bp = reinterpret_cast<const uint32_t*>(b);
    asm volatile(
        "mma.sync.aligned.m16n8k8.row.col.f32.tf32.tf32.f32 "
        "{%0,%1,%2,%3}, {%4,%5,%6,%7}, {%8,%9}, {%0,%1,%2,%3};"
        : "+f"(c[0]), "+f"(c[1]), "+f"(c[2]), "+f"(c[3])
        : "r"(A[0]), "r"(A[1]), "r"(A[2]), "r"(A[3]), "r"(Bp[0]), "r"(Bp[1]));
}

// fp16 mma m16n8k16 (big GEMMs) — 2x K per instruction vs tf32 k8
__device__ __forceinline__ void mma_f16(float c[4], const uint32_t a[4],
                                        uint32_t b0, uint32_t b1) {
    asm volatile(
        "mma.sync.aligned.m16n8k16.row.col.f32.f16.f16.f32 "
        "{%0,%1,%2,%3}, {%4,%5,%6,%7}, {%8,%9}, {%0,%1,%2,%3};"
        : "+f"(c[0]), "+f"(c[1]), "+f"(c[2]), "+f"(c[3])
        : "r"(a[0]), "r"(a[1]), "r"(a[2]), "r"(a[3]), "r"(b0), "r"(b1));
}

enum { EPI_QKV3 = 0, EPI_BIASRES = 3, EPI_GELU = 4 };

// ===========================================================================
// gemm_h: fp16 GEMM, C[M,N] = A[M,K] @ Wpacked^T (+epilogue).
// CTA 128x256x32, 256 thr, 8 warps (2M x 4N), warp tile 64x64.
// mma m16n8k16: 2 k-steps per 32-ktile, 64 mmas/warp/ktile (half of tf32).
// A: fp16 row-major; smem b32-stride 20 (all-32-bank-distinct fragment loads).
// B: fragment-packed fp16: per (ktile, n8): 32 lanes x 4 b32:
//   b32 idx = ((kt*NB8tot + n8)*32 + g*4 + t)*4 + (ks2*2 + h2), f16 pos = k&1
//   -> one LDS.128 per n8 per ktile, naturally conflict-free.
// 3-stage cp.async pipeline.
// ===========================================================================
#define GH_AS 20
#define GH_A_B32 (128*GH_AS)                 // 2560 b32 per stage
#define GH_B_B32 4096                        // 256n x 16 b32 per stage
#define GH_SMEM (3*(GH_A_B32+GH_B_B32)*4)    // 79872 bytes

template<int EPI>
__global__ void __launch_bounds__(256, 1) gemm_h(
    const __half* __restrict__ A, const __half* __restrict__ Bp,
    float* __restrict__ C0, float* __restrict__ C1, float* __restrict__ C2,
    __half* __restrict__ Ch,
    int K, int NB8tot, int ldc,
    const float* __restrict__ bias0, const float* __restrict__ bias1,
    const float* __restrict__ bias2, const float* __restrict__ extra, float scale)
{
    extern __shared__ uint32_t smu[];
    uint32_t* sA = smu;
    uint32_t* sB = smu + 3 * GH_A_B32;

    const int tid = threadIdx.x;
    const int ntk = K >> 5;

    const __half* Ab = A + (long)blockIdx.y * 128 * K;
    const uint32_t* Bg0 = (const uint32_t*)Bp + (long)blockIdx.x * 4096;

    auto issue = [&](int kt, int stg) {
        uint32_t* sa = sA + stg * GH_A_B32;
        const __half* ag = Ab + kt * 32;
#pragma unroll
        for (int i = 0; i < 2; i++) {
            int c = tid + i * 256;               // 0..511 (16B chunks of A tile)
            int r = c >> 2, ch = c & 3;
            cpa16(sa + r * GH_AS + ch * 4, ag + (long)r * K + ch * 8);
        }
        uint32_t* sb = sB + stg * GH_B_B32;
        const uint32_t* bg = Bg0 + (long)kt * NB8tot * 128;
#pragma unroll
        for (int i = 0; i < 4; i++) {
            int c = tid + i * 256;               // 0..1023: linear copy
            cpa16(sb + c * 4, bg + c * 4);
        }
    };

    const int warp = tid >> 5, lane = tid & 31;
    const int wm = (warp & 1) * 64;
    const int wnidx = warp >> 1;
    const int g = lane >> 2, t = lane & 3;

    float acc[4][8][4];
#pragma unroll
    for (int mt = 0; mt < 4; mt++)
#pragma unroll
        for (int nt = 0; nt < 8; nt++)
#pragma unroll
            for (int i = 0; i < 4; i++) acc[mt][nt][i] = 0.f;

    issue(0, 0); cp_commit();
    issue(1, 1); cp_commit();

    for (int it = 0; it < ntk; ++it) {
        const int stg = it % 3;
        if (it + 2 < ntk) issue(it + 2, (it + 2) % 3);
        cp_commit();
        cp_wait2();
        __syncthreads();

        const uint32_t* sa  = sA + stg * GH_A_B32;
        const uint32_t* sbw = sB + stg * GH_B_B32 + wnidx * 1024 + lane * 4;

        uint4 bf[8];
#pragma unroll
        for (int nt = 0; nt < 8; nt++)
            bf[nt] = *(const uint4*)(sbw + nt * 128);

        uint32_t af[2][4][4];
#pragma unroll
        for (int ks = 0; ks < 2; ks++)
#pragma unroll
            for (int mt = 0; mt < 4; mt++) {
                const int r0 = wm + mt * 16 + g;
                af[ks][mt][0] = sa[r0 * GH_AS + ks * 8 + t];
                af[ks][mt][1] = sa[(r0 + 8) * GH_AS + ks * 8 + t];
                af[ks][mt][2] = sa[r0 * GH_AS + ks * 8 + t + 4];
                af[ks][mt][3] = sa[(r0 + 8) * GH_AS + ks * 8 + t + 4];
            }

#pragma unroll
        for (int mt = 0; mt < 4; mt++)
#pragma unroll
            for (int nt = 0; nt < 8; nt++)
                mma_f16(acc[mt][nt], af[0][mt], bf[nt].x, bf[nt].y);
#pragma unroll
        for (int mt = 0; mt < 4; mt++)
#pragma unroll
            for (int nt = 0; nt < 8; nt++)
                mma_f16(acc[mt][nt], af[1][mt], bf[nt].z, bf[nt].w);
        __syncthreads();
    }

    // ---------------- epilogue ----------------
    const int wn = wnidx * 64;
    const int nbase = blockIdx.x * 256;
    const int mbase = blockIdx.y * 128 + wm;

    float* dst = C0;
    const float* bs = bias0;
    float sc = scale;
    int nloc = nbase;
    if (EPI == EPI_QKV3) {
        const int seg = nbase >> 11;
        nloc = nbase & 2047;
        if (seg == 1) { dst = C1; bs = bias1; sc = 1.0f; }
        else if (seg == 2) { dst = C2; bs = bias2; sc = 1.0f; }
    }

#pragma unroll
    for (int mt = 0; mt < 4; mt++) {
#pragma unroll
        for (int half = 0; half < 2; half++) {
            const int row = mbase + mt * 16 + g + half * 8;
            const long crow = (long)row * ldc;
#pragma unroll
            for (int nt = 0; nt < 8; nt++) {
                const int cc = wn + nt * 8 + 2 * t;
                const int col = nloc + cc;
                float v0 = acc[mt][nt][half * 2 + 0];
                float v1 = acc[mt][nt][half * 2 + 1];
                if (EPI == EPI_QKV3) {
                    v0 = to_tf32((v0 + bs[col]) * sc);
                    v1 = to_tf32((v1 + bs[col + 1]) * sc);
                    *(float2*)(dst + crow + col) = make_float2(v0, v1);
                } else if (EPI == EPI_BIASRES) {
                    v0 += bs[col]     + extra[crow + col];
                    v1 += bs[col + 1] + extra[crow + col + 1];
                    *(float2*)(dst + crow + col) = make_float2(v0, v1);
                } else if (EPI == EPI_GELU) {
                    v0 += bs[col];
                    v1 += bs[col + 1];
                    v0 = 0.5f * v0 * (1.f + erff(v0 * 0.7071067811865476f));
                    v1 = 0.5f * v1 * (1.f + erff(v1 * 0.7071067811865476f));
                    *(__half2*)(Ch + crow + col) = __floats2half2_rn(v0, v1);
                }
            }
        }
    }
}

// ===========================================================================
// Flash attention (R10-proven, tf32): grid (8 qblocks, 64 bh), 256 thr/8 warps,
// warp owns 16 full q-rows; KB=64 double-buffered K; online softmax via t-lane
// shuffles; P through per-warp smem. Output written as fp16 (A for Wo GEMM).
// ===========================================================================
#define FA_KB 64
#define FA_QSTR 132
#define FA_KSTR 132
#define FA_VSTR 136
#define FA_PSTR 68
#define FA_SQ 0
#define FA_SK 16896
#define FA_SV 33792
#define FA_SP 42496
#define FA_SM 51200
#define FA_TOTALF 52224
#define FA_SMEM (FA_TOTALF*4)     // 208896 bytes

__global__ void __launch_bounds__(256, 1) flash_kernel(
    const float* __restrict__ Qg, const float* __restrict__ Kg,
    const float* __restrict__ Vg, const float* __restrict__ amask,
    __half* __restrict__ Og)
{
    extern __shared__ float sm[];
    const int tid = threadIdx.x;
    const int qb = blockIdx.x, bh = blockIdx.y;
    const int b = bh >> 4, h = bh & 15;
    const long qrow0 = (long)b * SS + qb * 128;

    for (int i = tid; i < SS; i += 256)
        sm[FA_SM + i] = (amask[b * SS + i] == 0.f) ? -3.4028234663852886e38f : 0.f;

    {
        const float* qg = Qg + qrow0 * DD + h * HDIM;
#pragma unroll
        for (int i = 0; i < 16; i++) {
            int c = tid + i * 256;
            int r = c >> 5, ch = c & 31;
            cpa16(sm + FA_SQ + r * FA_QSTR + ch * 4, qg + (long)r * DD + ch * 4);
        }
        cp_commit();
    }

    auto loadK = [&](int kb, int buf) {
        const float* kg = Kg + ((long)b * SS + kb * FA_KB) * DD + h * HDIM;
        float* dstp = sm + FA_SK + buf * 8448;
#pragma unroll
        for (int i = 0; i < 8; i++) {
            int c = tid + i * 256;
            int r = c >> 5, ch = c & 31;
            cpa16(dstp + r * FA_KSTR + ch * 4, kg + (long)r * DD + ch * 4);
        }
    };
    auto loadV = [&](int kb) {
        const float* vg = Vg + ((long)b * SS + kb * FA_KB) * DD + h * HDIM;
        float* dstp = sm + FA_SV;
#pragma unroll
        for (int i = 0; i < 8; i++) {
            int c = tid + i * 256;
            int r = c >> 5, ch = c & 31;
            cpa16(dstp + r * FA_VSTR + ch * 4, vg + (long)r * DD + ch * 4);
        }
    };
    loadK(0, 0); cp_commit();
    loadV(0);    cp_commit();

    const int w = tid >> 5, lane = tid & 31;
    const int g = lane >> 2, t = lane & 3;

    float m0 = -3.4028234663852886e38f, m1 = -3.4028234663852886e38f;
    float l0 = 0.f, l1 = 0.f;
    float o[16][4];
#pragma unroll
    for (int nt = 0; nt < 16; nt++)
#pragma unroll
        for (int i = 0; i < 4; i++) o[nt][i] = 0.f;

    const float* sq = sm + FA_SQ + (w * 16 + g) * FA_QSTR;
    float* sp = sm + FA_SP + (w * 16 + g) * FA_PSTR;

    for (int kb = 0; kb < SS / FA_KB; kb++) {
        const int buf = kb & 1;
        cp_wait1();
        __syncthreads();
        if (kb + 1 < SS / FA_KB) loadK(kb + 1, buf ^ 1);
        cp_commit();

        const float* sk = sm + FA_SK + buf * 8448;
        float s[8][4];
#pragma unroll
        for (int nt = 0; nt < 8; nt++)
#pragma unroll
            for (int i = 0; i < 4; i++) s[nt][i] = 0.f;
#pragma unroll
        for (int ks = 0; ks < 16; ks++) {
            float af[4];
            af[0] = sq[ks * 8 + t];
            af[1] = sq[8 * FA_QSTR + ks * 8 + t];
            af[2] = sq[ks * 8 + t + 4];
            af[3] = sq[8 * FA_QSTR + ks * 8 + t + 4];
#pragma unroll
            for (int nt = 0; nt < 8; nt++) {
                float bfv[2];
                bfv[0] = sk[(nt * 8 + g) * FA_KSTR + ks * 8 + t];
                bfv[1] = sk[(nt * 8 + g) * FA_KSTR + ks * 8 + t + 4];
                mma_tf32(s[nt], af, bfv);
            }
        }

        float mn0 = m0, mn1 = m1;
#pragma unroll
        for (int nt = 0; nt < 8; nt++) {
            float ma = sm[FA_SM + kb * FA_KB + nt * 8 + 2 * t];
            float mb = sm[FA_SM + kb * FA_KB + nt * 8 + 2 * t + 1];
            s[nt][0] += ma; s[nt][1] += mb; s[nt][2] += ma; s[nt][3] += mb;
            mn0 = fmaxf(mn0, fmaxf(s[nt][0], s[nt][1]));
            mn1 = fmaxf(mn1, fmaxf(s[nt][2], s[nt][3]));
        }
        mn0 = fmaxf(mn0, __shfl_xor_sync(0xffffffffu, mn0, 1));
        mn0 = fmaxf(mn0, __shfl_xor_sync(0xffffffffu, mn0, 2));
        mn1 = fmaxf(mn1, __shfl_xor_sync(0xffffffffu, mn1, 1));
        mn1 = fmaxf(mn1, __shfl_xor_sync(0xffffffffu, mn1, 2));
        const float sc0 = __expf(m0 - mn0), sc1 = __expf(m1 - mn1);
        m0 = mn0; m1 = mn1;

        float ls0 = 0.f, ls1 = 0.f;
#pragma unroll
        for (int nt = 0; nt < 8; nt++) {
            float p0 = __expf(s[nt][0] - m0), p1 = __expf(s[nt][1] - m0);
            float p2 = __expf(s[nt][2] - m1), p3 = __expf(s[nt][3] - m1);
            ls0 += p0 + p1; ls1 += p2 + p3;
            *(float2*)(sp + nt * 8 + 2 * t) = make_float2(to_tf32(p0), to_tf32(p1));
            *(float2*)(sp + 8 * FA_PSTR + nt * 8 + 2 * t) = make_float2(to_tf32(p2), to_tf32(p3));
        }
        ls0 += __shfl_xor_sync(0xffffffffu, ls0, 1);
        ls0 += __shfl_xor_sync(0xffffffffu, ls0, 2);
        ls1 += __shfl_xor_sync(0xffffffffu, ls1, 1);
        ls1 += __shfl_xor_sync(0xffffffffu, ls1, 2);
        l0 = l0 * sc0 + ls0;
        l1 = l1 * sc1 + ls1;
#pragma unroll
        for (int nt = 0; nt < 16; nt++) {
            o[nt][0] *= sc0; o[nt][1] *= sc0;
            o[nt][2] *= sc1; o[nt][3] *= sc1;
        }

        cp_wait1();
        __syncthreads();

        const float* sv = sm + FA_SV;
#pragma unroll
        for (int ks = 0; ks < 8; ks++) {
            float af[4];
            af[0] = sp[ks * 8 + t];
            af[1] = sp[8 * FA_PSTR + ks * 8 + t];
            af[2] = sp[ks * 8 + t + 4];
            af[3] = sp[8 * FA_PSTR + ks * 8 + t + 4];
#pragma unroll
            for (int nt = 0; nt < 16; nt++) {
                float bfv[2];
                bfv[0] = sv[(ks * 8 + t) * FA_VSTR + nt * 8 + g];
                bfv[1] = sv[(ks * 8 + t + 4) * FA_VSTR + nt * 8 + g];
                mma_tf32(o[nt], af, bfv);
            }
        }
        __syncthreads();
        if (kb + 1 < SS / FA_KB) loadV(kb + 1);
        cp_commit();
    }

    const float inv0 = 1.f / l0, inv1 = 1.f / l1;
    __half* og = Og + (qrow0 + w * 16 + g) * DD + h * HDIM;
#pragma unroll
    for (int nt = 0; nt < 16; nt++) {
        *(__half2*)(og + nt * 8 + 2 * t) =
            __floats2half2_rn(o[nt][0] * inv0, o[nt][1] * inv0);
        *(__half2*)(og + 8 * DD + nt * 8 + 2 * t) =
            __floats2half2_rn(o[nt][2] * inv1, o[nt][3] * inv1);
    }
}

// ---------------------------------------------------------------------------
// LayerNorm: fp32 in, fp16 (rn) out
// ---------------------------------------------------------------------------
__global__ void ln_kernel(const float* __restrict__ x, const float* __restrict__ w,
                          const float* __restrict__ b, __half* __restrict__ out)
{
    __shared__ float s1[8], s2[8];
    const int row = blockIdx.x, tid = threadIdx.x;
    const int lane = tid & 31, wid = tid >> 5;
    const float4* xr = (const float4*)(x + (long)row * DD);
    float4 v0 = xr[tid], v1 = xr[tid + 256];

    float s = v0.x + v0.y + v0.z + v0.w + v1.x + v1.y + v1.z + v1.w;
    float q = v0.x*v0.x + v0.y*v0.y + v0.z*v0.z + v0.w*v0.w
            + v1.x*v1.x + v1.y*v1.y + v1.z*v1.z + v1.w*v1.w;
#pragma unroll
    for (int o = 16; o; o >>= 1) {
        s += __shfl_xor_sync(0xffffffffu, s, o);
        q += __shfl_xor_sync(0xffffffffu, q, o);
    }
    if (lane == 0) { s1[wid] = s; s2[wid] = q; }
    __syncthreads();
    if (tid < 8) {
        s = s1[tid]; q = s2[tid];
#pragma unroll
        for (int o = 4; o; o >>= 1) {
            s += __shfl_xor_sync(0xffu, s, o);
            q += __shfl_xor_sync(0xffu, q, o);
        }
        if (tid == 0) { s1[0] = s; s2[0] = q; }
    }
    __syncthreads();
    const float mu = s1[0] * (1.f / DD);
    const float var = s2[0] * (1.f / DD) - mu * mu;
    const float r = rsqrtf(var + 1e-5f);

    const int c0 = tid * 4, c1 = (tid + 256) * 4;
    __half2* orow = (__half2*)(out + (long)row * DD);
    orow[tid * 2 + 0] = __floats2half2_rn((v0.x - mu) * r * w[c0+0] + b[c0+0],
                                          (v0.y - mu) * r * w[c0+1] + b[c0+1]);
    orow[tid * 2 + 1] = __floats2half2_rn((v0.z - mu) * r * w[c0+2] + b[c0+2],
                                          (v0.w - mu) * r * w[c0+3] + b[c0+3]);
    orow[(tid + 256) * 2 + 0] = __floats2half2_rn((v1.x - mu) * r * w[c1+0] + b[c1+0],
                                                  (v1.y - mu) * r * w[c1+1] + b[c1+1]);
    orow[(tid + 256) * 2 + 1] = __floats2half2_rn((v1.z - mu) * r * w[c1+2] + b[c1+2],
                                                  (v1.w - mu) * r * w[c1+3] + b[c1+3]);
}

// ---------------------------------------------------------------------------
// Weight round+pack to fp16 m16n8k16 B-fragment layout.
//   element (n,k): g=n&7, n8=n>>3, kt=k>>5, kk=k&31, ks2=kk>>4, r=kk&15,
//   h2=r>>3, t'=(r>>1)&3, pos=r&1
//   b32 idx = ((kt*NB8tot+n8)*32 + g*4+t')*4 + ks2*2 + h2 ; f16 = b32*2+pos
// ---------------------------------------------------------------------------
__device__ __forceinline__ void pack4h(const float* __restrict__ src, __half* __restrict__ dst,
                                       int K, int NB8tot, int n8off, long s)
{
    const int kq = K >> 2;
    const int n = (int)(s / kq);
    const int k4 = (int)(s - (long)n * kq);
    float4 v = ((const float4*)src)[s];
    float vals[4] = {v.x, v.y, v.z, v.w};
    const int gg = n & 7;
    const long n8 = (n >> 3) + n8off;
#pragma unroll
    for (int c = 0; c < 4; c++) {
        const int k = k4 * 4 + c;
        const int kt = k >> 5, kk = k & 31;
        const int ks2 = kk >> 4, r = kk & 15;
        const int h2 = r >> 3, tp = (r >> 1) & 3, pos = r & 1;
        const long b32 = (((long)kt * NB8tot + n8) * 32 + gg * 4 + tp) * 4 + ks2 * 2 + h2;
        dst[b32 * 2 + pos] = __float2half_rn(vals[c]);
    }
}

__global__ void pack_attn(
    const float* __restrict__ Wq, const float* __restrict__ Wk,
    const float* __restrict__ Wv, const float* __restrict__ Wo,
    __half* __restrict__ dqkv, __half* __restrict__ dwo)
{
    const long M1 = 1048576;
    const long i = (long)blockIdx.x * 256 + threadIdx.x;
    if      (i < 1*M1) pack4h(Wq, dqkv, DD, 768, 0,   i);
    else if (i < 2*M1) pack4h(Wk, dqkv, DD, 768, 256, i - 1*M1);
    else if (i < 3*M1) pack4h(Wv, dqkv, DD, 768, 512, i - 2*M1);
    else               pack4h(Wo, dwo,  DD, 256, 0,   i - 3*M1);
}

__global__ void pack_mlp(
    const float* __restrict__ W1, const float* __restrict__ W2,
    __half* __restrict__ dw1, __half* __restrict__ dw2)
{
    const long M4 = 4194304;
    const long i = (long)blockIdx.x * 256 + threadIdx.x;
    if (i < M4) pack4h(W1, dw1, DD, 1024, 0, i);
    else        pack4h(W2, dw2, II, 256, 0,  i - M4);
}

// ---------------------------------------------------------------------------
// Host launch
// ---------------------------------------------------------------------------
extern "C" void kernel_launch(void* const* d_in, const int* in_sizes, int n_in,
                              void* d_out, int out_size)
{
    const float* hid   = (const float*)d_in[1];
    const float* amask = (const float*)d_in[2];
    const float* Wq = (const float*)d_in[4];  const float* bq = (const float*)d_in[5];
    const float* Wk = (const float*)d_in[6];  const float* bk = (const float*)d_in[7];
    const float* Wv = (const float*)d_in[8];  const float* bv = (const float*)d_in[9];
    const float* Wo = (const float*)d_in[10]; const float* bo = (const float*)d_in[11];
    const float* l1w = (const float*)d_in[12]; const float* l1b = (const float*)d_in[13];
    const float* l2w = (const float*)d_in[14]; const float* l2b = (const float*)d_in[15];
    const float* W1 = (const float*)d_in[16]; const float* b1 = (const float*)d_in[17];
    const float* W2 = (const float*)d_in[18]; const float* b2 = (const float*)d_in[19];
    float* out = (float*)d_out;

    void* p;
    cudaGetSymbolAddress(&p, g_xln1h); __half* xln1h = (__half*)p;
    cudaGetSymbolAddress(&p, g_q);     float* q    = (float*)p;
    cudaGetSymbolAddress(&p, g_k);     float* k    = (float*)p;
    cudaGetSymbolAddress(&p, g_v);     float* v    = (float*)p;
    cudaGetSymbolAddress(&p, g_attnh); __half* attnh = (__half*)p;
    cudaGetSymbolAddress(&p, g_hidden);float* hd2  = (float*)p;
    cudaGetSymbolAddress(&p, g_yln2h); __half* yln2h = (__half*)p;
    cudaGetSymbolAddress(&p, g_midh);  __half* midh = (__half*)p;
    cudaGetSymbolAddress(&p, g_wqkv);  __half* wqkv = (__half*)p;
    cudaGetSymbolAddress(&p, g_wo);    __half* wo   = (__half*)p;
    cudaGetSymbolAddress(&p, g_w1);    __half* w1   = (__half*)p;
    cudaGetSymbolAddress(&p, g_w2);    __half* w2   = (__half*)p;

    cudaFuncSetAttribute((const void*)gemm_h<EPI_QKV3>,   cudaFuncAttributeMaxDynamicSharedMemorySize, GH_SMEM);
    cudaFuncSetAttribute((const void*)gemm_h<EPI_BIASRES>,cudaFuncAttributeMaxDynamicSharedMemorySize, GH_SMEM);
    cudaFuncSetAttribute((const void*)gemm_h<EPI_GELU>,   cudaFuncAttributeMaxDynamicSharedMemorySize, GH_SMEM);
    cudaFuncSetAttribute((const void*)flash_kernel,       cudaFuncAttributeMaxDynamicSharedMemorySize, FA_SMEM);

    const float qscale = 0.08838834764831845f;  // 128^-0.5

    // 1) pack attn weights (fp16 fragments)
    pack_attn<<<16384, 256>>>(Wq, Wk, Wv, Wo, wqkv, wo);
    // 2) pack mlp weights
    pack_mlp<<<32768, 256>>>(W1, W2, w1, w2);
    // 3) LN1 -> fp16
    ln_kernel<<<MTOK, 256>>>(hid, l1w, l1b, xln1h);
    // 4) fused QKV projection [4096 x 6144], fp16 mma  <-- ncu profiles this
    gemm_h<EPI_QKV3><<<dim3(24, 32), 256, GH_SMEM>>>(
        xln1h, wqkv, q, k, v, nullptr, DD, 768, DD, bq, bk, bv, nullptr, qscale);
    // 5) flash attention (tf32), writes attn fp16
    flash_kernel<<<dim3(8, BB*HH), 256, FA_SMEM>>>(q, k, v, amask, attnh);
    // 6) hidden = residual + attn @ Wo^T + bo
    gemm_h<EPI_BIASRES><<<dim3(8, 32), 256, GH_SMEM>>>(
        attnh, wo, hd2, nullptr, nullptr, nullptr, DD, 256, DD, bo, nullptr, nullptr, hid, 1.0f);
    // 7) LN2 -> fp16
    ln_kernel<<<MTOK, 256>>>(hd2, l2w, l2b, yln2h);
    // 8) mid = gelu(yln2 @ W1^T + b1) -> fp16
    gemm_h<EPI_GELU><<<dim3(32, 32), 256, GH_SMEM>>>(
        yln2h, w1, nullptr, nullptr, nullptr, midh, DD, 1024, II, b1, nullptr, nullptr, nullptr, 1.0f);
    // 9) out = hidden + mid @ W2^T + b2 (K=8192)
    gemm_h<EPI_BIASRES><<<dim3(8, 32), 256, GH_SMEM>>>(
        midh, w2, out, nullptr, nullptr, nullptr, II, 256, DD, b2, nullptr, nullptr, hd2, 1.0f);
}